// round 1
// baseline (speedup 1.0000x reference)
#include <cuda_runtime.h>

#define HIDW 3072
#define DHW  128
#define NHW  24
#define S_ALL 1536
#define TXTN 512
#define IMGN 1024

// Scratch: 11520 rows x 3072 floats (~141.6 MB), carved by row offsets.
__device__ float g_buf[11520ull * 3072ull];

#define O_Q     0
#define O_K     1024
#define O_EQ    2048
#define O_EK    2560
#define O_IPK   3072
#define O_IPV   3200
#define O_IPQ   3328
#define O_QF    4352
#define O_KF    5888
#define O_VF    7424
#define O_ATTN  8960
#define O_IPOUT 10496

// ---------------------------------------------------------------------------
// GEMM: C[M,N] = X[M,K] @ W[N,K]^T + bias[N]
// Tiles: BM=64, BN=128, BK=16. 256 threads, each computes 4x8.
// Requires M%64==0, N%128==0, K%16==0 (true for all shapes here).
// ---------------------------------------------------------------------------
__global__ __launch_bounds__(256) void gemm_kernel(
    const float* __restrict__ X, const float* __restrict__ W,
    const float* __restrict__ bias, float* __restrict__ C,
    int M, int N, int K)
{
    __shared__ float As[16][68];
    __shared__ float Bs[16][132];

    const int tid = threadIdx.x;
    const int tx = tid & 15;        // 0..15 -> 8 output cols each
    const int ty = tid >> 4;        // 0..15 -> 4 output rows each
    const int bm = blockIdx.y * 64;
    const int bn = blockIdx.x * 128;

    const int lr = tid >> 2;        // 0..63
    const int lk = (tid & 3) << 2;  // 0,4,8,12

    const float* xp  = X + (size_t)(bm + lr) * K + lk;
    const float* wp0 = W + (size_t)(bn + lr) * K + lk;
    const float* wp1 = W + (size_t)(bn + lr + 64) * K + lk;

    float acc[4][8];
#pragma unroll
    for (int i = 0; i < 4; i++)
#pragma unroll
        for (int j = 0; j < 8; j++) acc[i][j] = 0.f;

    for (int k0 = 0; k0 < K; k0 += 16) {
        float4 xa = *(const float4*)(xp + k0);
        float4 wa = *(const float4*)(wp0 + k0);
        float4 wb = *(const float4*)(wp1 + k0);
        As[lk + 0][lr] = xa.x; As[lk + 1][lr] = xa.y;
        As[lk + 2][lr] = xa.z; As[lk + 3][lr] = xa.w;
        Bs[lk + 0][lr] = wa.x; Bs[lk + 1][lr] = wa.y;
        Bs[lk + 2][lr] = wa.z; Bs[lk + 3][lr] = wa.w;
        Bs[lk + 0][lr + 64] = wb.x; Bs[lk + 1][lr + 64] = wb.y;
        Bs[lk + 2][lr + 64] = wb.z; Bs[lk + 3][lr + 64] = wb.w;
        __syncthreads();

#pragma unroll
        for (int kk = 0; kk < 16; kk++) {
            float4 a  = *(const float4*)&As[kk][ty << 2];
            float4 b0 = *(const float4*)&Bs[kk][tx << 3];
            float4 b1 = *(const float4*)&Bs[kk][(tx << 3) + 4];
            float av[4] = {a.x, a.y, a.z, a.w};
            float bv[8] = {b0.x, b0.y, b0.z, b0.w, b1.x, b1.y, b1.z, b1.w};
#pragma unroll
            for (int i = 0; i < 4; i++)
#pragma unroll
                for (int j = 0; j < 8; j++)
                    acc[i][j] += av[i] * bv[j];
        }
        __syncthreads();
    }

#pragma unroll
    for (int i = 0; i < 4; i++) {
        float* crow = C + (size_t)(bm + (ty << 2) + i) * N + bn + (tx << 3);
#pragma unroll
        for (int j = 0; j < 8; j++)
            crow[j] = acc[i][j] + bias[bn + (tx << 3) + j];
    }
}

// ---------------------------------------------------------------------------
// RMS norm per 128-dim head chunk. grid (L, 24), block 128.
// ---------------------------------------------------------------------------
__global__ void rms_kernel(const float* __restrict__ X, const float* __restrict__ w,
                           float* __restrict__ Y)
{
    const int row = blockIdx.x;
    const int h = blockIdx.y;
    const int d = threadIdx.x;
    const size_t idx = (size_t)row * HIDW + h * DHW + d;
    float x = X[idx];
    float v = x * x;
#pragma unroll
    for (int off = 16; off > 0; off >>= 1)
        v += __shfl_xor_sync(0xffffffffu, v, off);
    __shared__ float ws[4];
    const int lane = d & 31, wid = d >> 5;
    if (lane == 0) ws[wid] = v;
    __syncthreads();
    float total = ws[0] + ws[1] + ws[2] + ws[3];
    float r = rsqrtf(total * (1.0f / 128.0f) + 1e-6f);
    Y[idx] = x * r * w[d];
}

// ---------------------------------------------------------------------------
// RoPE in place. grid (1536, 24), block 128. cos/sin: [1536,128].
// ---------------------------------------------------------------------------
__global__ void rope_kernel(float* __restrict__ X, const float* __restrict__ cosT,
                            const float* __restrict__ sinT)
{
    __shared__ float sx[128];
    const int row = blockIdx.x;
    const int h = blockIdx.y;
    const int d = threadIdx.x;
    const size_t idx = (size_t)row * HIDW + h * DHW + d;
    float x = X[idx];
    sx[d] = x;
    __syncthreads();
    float c = cosT[row * DHW + d];
    float s = sinT[row * DHW + d];
    float xr = (d & 1) ? sx[d - 1] : -sx[d + 1];
    X[idx] = x * c + xr * s;
}

// ---------------------------------------------------------------------------
// Attention: 8 query rows x 1 head per block. 256 threads.
// smem: q tile (8*128) | scores (8*nkv) | red (256) | rinv (8)
// ---------------------------------------------------------------------------
__global__ __launch_bounds__(256) void attn_kernel(
    const float* __restrict__ Q, const float* __restrict__ Km,
    const float* __restrict__ Vm, float* __restrict__ O, int nkv)
{
    extern __shared__ float sm[];
    float* sq   = sm;                  // 1024
    float* ss   = sm + 1024;           // 8*nkv
    float* red  = ss + 8 * nkv;        // 256
    float* rinv = red + 256;           // 8

    const int h = blockIdx.y;
    const int r0 = blockIdx.x * 8;
    const int tid = threadIdx.x;

    for (int i = tid; i < 1024; i += 256) {
        int r = i >> 7, d = i & 127;
        sq[i] = Q[(size_t)(r0 + r) * HIDW + h * DHW + d];
    }
    __syncthreads();

    const float scale = 0.08838834764831845f;  // 1/sqrt(128)

    // scores
    for (int k = tid; k < nkv; k += 256) {
        const float4* kr = (const float4*)(Km + (size_t)k * HIDW + h * DHW);
        float acc[8] = {0.f, 0.f, 0.f, 0.f, 0.f, 0.f, 0.f, 0.f};
#pragma unroll 8
        for (int d4 = 0; d4 < 32; d4++) {
            float4 kv = kr[d4];
#pragma unroll
            for (int r = 0; r < 8; r++) {
                float4 qv = ((const float4*)sq)[r * 32 + d4];
                acc[r] += qv.x * kv.x + qv.y * kv.y + qv.z * kv.z + qv.w * kv.w;
            }
        }
#pragma unroll
        for (int r = 0; r < 8; r++) ss[r * nkv + k] = acc[r] * scale;
    }
    __syncthreads();

    // softmax per row
    for (int r = 0; r < 8; r++) {
        float m = -1e30f;
        for (int k = tid; k < nkv; k += 256) m = fmaxf(m, ss[r * nkv + k]);
        red[tid] = m;
        __syncthreads();
        for (int s = 128; s > 0; s >>= 1) {
            if (tid < s) red[tid] = fmaxf(red[tid], red[tid + s]);
            __syncthreads();
        }
        m = red[0];
        __syncthreads();
        float sum = 0.f;
        for (int k = tid; k < nkv; k += 256) {
            float e = __expf(ss[r * nkv + k] - m);
            ss[r * nkv + k] = e;
            sum += e;
        }
        red[tid] = sum;
        __syncthreads();
        for (int s = 128; s > 0; s >>= 1) {
            if (tid < s) red[tid] += red[tid + s];
            __syncthreads();
        }
        if (tid == 0) rinv[r] = 1.0f / red[0];
        __syncthreads();
    }

    // PV: warp w handles row r=w, lane handles 4 dims
    const int d4i = tid & 31;
    const int r = tid >> 5;
    float4 acc = make_float4(0.f, 0.f, 0.f, 0.f);
    const float* srow = ss + r * nkv;
    for (int k = 0; k < nkv; k++) {
        float s = srow[k];
        float4 vv = ((const float4*)(Vm + (size_t)k * HIDW + h * DHW))[d4i];
        acc.x += s * vv.x; acc.y += s * vv.y;
        acc.z += s * vv.z; acc.w += s * vv.w;
    }
    float inv = rinv[r];
    float4* orow = (float4*)(O + (size_t)(r0 + r) * HIDW + h * DHW);
    orow[d4i] = make_float4(acc.x * inv, acc.y * inv, acc.z * inv, acc.w * inv);
}

// ---------------------------------------------------------------------------
// img += ip_out * mask  (BBOX = (8,8,24,24) on 32x32 grid)
// ---------------------------------------------------------------------------
__global__ void maskadd_kernel(float* __restrict__ A, const float* __restrict__ IP)
{
    const int i = blockIdx.x;   // img token 0..1023
    const int y = i >> 5, x = i & 31;
    if (y < 8 || y >= 24 || x < 8 || x >= 24) return;
    for (int c = threadIdx.x; c < HIDW; c += 256)
        A[(size_t)i * HIDW + c] += IP[(size_t)i * HIDW + c];
}

// ---------------------------------------------------------------------------
extern "C" void kernel_launch(void* const* d_in, const int* in_sizes, int n_in,
                              void* d_out, int out_size)
{
    const float* hs    = (const float*)d_in[0];
    const float* enc   = (const float*)d_in[1];
    const float* ip    = (const float*)d_in[2];
    const float* cosT  = (const float*)d_in[3];
    const float* sinT  = (const float*)d_in[4];
    const float* Wq    = (const float*)d_in[5];
    const float* bq    = (const float*)d_in[6];
    const float* Wk    = (const float*)d_in[7];
    const float* bk    = (const float*)d_in[8];
    const float* Wv    = (const float*)d_in[9];
    const float* bv    = (const float*)d_in[10];
    const float* nqw   = (const float*)d_in[11];
    const float* nkw   = (const float*)d_in[12];
    const float* Wqa   = (const float*)d_in[13];
    const float* bqa   = (const float*)d_in[14];
    const float* Wka   = (const float*)d_in[15];
    const float* bka   = (const float*)d_in[16];
    const float* Wva   = (const float*)d_in[17];
    const float* bva   = (const float*)d_in[18];
    const float* naqw  = (const float*)d_in[19];
    const float* nakw  = (const float*)d_in[20];
    const float* Wout  = (const float*)d_in[21];
    const float* bout  = (const float*)d_in[22];
    const float* Waout = (const float*)d_in[23];
    const float* baout = (const float*)d_in[24];
    const float* Wkip  = (const float*)d_in[25];
    const float* bkip  = (const float*)d_in[26];
    const float* Wvip  = (const float*)d_in[27];
    const float* bvip  = (const float*)d_in[28];
    const float* nipq  = (const float*)d_in[29];
    const float* nipk  = (const float*)d_in[30];

    float* buf = nullptr;
    cudaGetSymbolAddress((void**)&buf, g_buf);

    float* Qb   = buf + (size_t)O_Q * HIDW;
    float* Kb   = buf + (size_t)O_K * HIDW;
    float* EQb  = buf + (size_t)O_EQ * HIDW;
    float* EKb  = buf + (size_t)O_EK * HIDW;
    float* IPKb = buf + (size_t)O_IPK * HIDW;
    float* IPVb = buf + (size_t)O_IPV * HIDW;
    float* IPQb = buf + (size_t)O_IPQ * HIDW;
    float* QFb  = buf + (size_t)O_QF * HIDW;
    float* KFb  = buf + (size_t)O_KF * HIDW;
    float* VFb  = buf + (size_t)O_VF * HIDW;
    float* ATb  = buf + (size_t)O_ATTN * HIDW;
    float* IPOb = buf + (size_t)O_IPOUT * HIDW;

    float* out_img = (float*)d_out;                       // 1024 x 3072
    float* out_enc = (float*)d_out + (size_t)IMGN * HIDW; // 512 x 3072

    const int smem_main = (1024 + 8 * 1536 + 256 + 8) * 4;  // 54304 B
    const int smem_ip   = (1024 + 8 * 128 + 256 + 8) * 4;
    cudaFuncSetAttribute(attn_kernel, cudaFuncAttributeMaxDynamicSharedMemorySize,
                         smem_main);

    dim3 blk(256);
    // Projections
    gemm_kernel<<<dim3(HIDW / 128, IMGN / 64), blk>>>(hs, Wq, bq, Qb, IMGN, HIDW, HIDW);
    gemm_kernel<<<dim3(HIDW / 128, IMGN / 64), blk>>>(hs, Wk, bk, Kb, IMGN, HIDW, HIDW);
    gemm_kernel<<<dim3(HIDW / 128, IMGN / 64), blk>>>(hs, Wv, bv, VFb + (size_t)TXTN * HIDW, IMGN, HIDW, HIDW);
    gemm_kernel<<<dim3(HIDW / 128, TXTN / 64), blk>>>(enc, Wqa, bqa, EQb, TXTN, HIDW, HIDW);
    gemm_kernel<<<dim3(HIDW / 128, TXTN / 64), blk>>>(enc, Wka, bka, EKb, TXTN, HIDW, HIDW);
    gemm_kernel<<<dim3(HIDW / 128, TXTN / 64), blk>>>(enc, Wva, bva, VFb, TXTN, HIDW, HIDW);
    gemm_kernel<<<dim3(HIDW / 128, 128 / 64), blk>>>(ip, Wkip, bkip, IPKb, 128, HIDW, 1152);
    gemm_kernel<<<dim3(HIDW / 128, 128 / 64), blk>>>(ip, Wvip, bvip, IPVb, 128, HIDW, 1152);

    // RMS norms
    rms_kernel<<<dim3(IMGN, NHW), 128>>>(Qb, nipq, IPQb);
    rms_kernel<<<dim3(128, NHW), 128>>>(IPKb, nipk, IPKb);
    rms_kernel<<<dim3(IMGN, NHW), 128>>>(Qb, nqw, QFb + (size_t)TXTN * HIDW);
    rms_kernel<<<dim3(IMGN, NHW), 128>>>(Kb, nkw, KFb + (size_t)TXTN * HIDW);
    rms_kernel<<<dim3(TXTN, NHW), 128>>>(EQb, naqw, QFb);
    rms_kernel<<<dim3(TXTN, NHW), 128>>>(EKb, nakw, KFb);

    // RoPE
    rope_kernel<<<dim3(S_ALL, NHW), 128>>>(QFb, cosT, sinT);
    rope_kernel<<<dim3(S_ALL, NHW), 128>>>(KFb, cosT, sinT);

    // Attention
    attn_kernel<<<dim3(S_ALL / 8, NHW), blk, smem_main>>>(QFb, KFb, VFb, ATb, S_ALL);
    attn_kernel<<<dim3(IMGN / 8, NHW), blk, smem_ip>>>(IPQb, IPKb, IPVb, IPOb, 128);

    // mask add on img part
    maskadd_kernel<<<IMGN, blk>>>(ATb + (size_t)TXTN * HIDW, IPOb);

    // Output projections
    gemm_kernel<<<dim3(HIDW / 128, IMGN / 64), blk>>>(ATb + (size_t)TXTN * HIDW, Wout, bout,
                                                      out_img, IMGN, HIDW, HIDW);
    gemm_kernel<<<dim3(HIDW / 128, TXTN / 64), blk>>>(ATb, Waout, baout,
                                                      out_enc, TXTN, HIDW, HIDW);
}

// round 6
// speedup vs baseline: 2.8693x; 2.8693x over previous
#include <cuda_runtime.h>
#include <cuda_bf16.h>

#define HIDW 3072
#define DHW  128
#define NHW  24
#define S_ALL 1536
#define TXTN 512
#define IMGN 1024

// fp32 scratch (intermediates)
__device__ float g_buf[11520ull * 3072ull];

#define O_Q     0
#define O_K     1024
#define O_EQ    2048
#define O_EK    2560
#define O_IPK   3072
#define O_IPV   3200
#define O_IPQ   3328
#define O_QF    4352
#define O_KF    5888
#define O_VF    7424
#define O_ATTN  8960
#define O_IPOUT 10496

// bf16 hi/lo arenas (weights + activations), element offsets below
#define BF_TOT 92160000ull
__device__ __nv_bfloat16 g_bh[BF_TOT];
__device__ __nv_bfloat16 g_bl[BF_TOT];

#define OFF_WQ    0ull
#define OFF_WK    9437184ull
#define OFF_WV    18874368ull
#define OFF_WQA   28311552ull
#define OFF_WKA   37748736ull
#define OFF_WVA   47185920ull
#define OFF_WOUT  56623104ull
#define OFF_WAOUT 66060288ull
#define OFF_WKIP  75497472ull
#define OFF_WVIP  79036416ull
#define OFF_HS    82575360ull
#define OFF_ENC   85721088ull
#define OFF_IP    87293952ull
#define OFF_ATI   87441408ull
#define OFF_ATE   90587136ull

// ---------------------------------------------------------------------------
// PTX helpers (plain sm_103-compatible: cp.async, ldmatrix, mma.sync)
// ---------------------------------------------------------------------------
__device__ __forceinline__ unsigned smem_u32(const void* p) {
    return (unsigned)__cvta_generic_to_shared(p);
}
__device__ __forceinline__ void cp_async16(unsigned s, const void* g) {
    asm volatile("cp.async.cg.shared.global [%0], [%1], 16;" :: "r"(s), "l"(g));
}
#define CP_COMMIT() asm volatile("cp.async.commit_group;" ::: "memory")

#define LDSM_X4(r, addr) \
    asm volatile("ldmatrix.sync.aligned.m8n8.x4.shared.b16 {%0,%1,%2,%3}, [%4];" \
                 : "=r"((r)[0]), "=r"((r)[1]), "=r"((r)[2]), "=r"((r)[3]) \
                 : "r"(addr))

__device__ __forceinline__ void mma16816(float* c, const unsigned* a,
                                         unsigned b0, unsigned b1) {
    asm volatile(
        "mma.sync.aligned.m16n8k16.row.col.f32.bf16.bf16.f32 "
        "{%0,%1,%2,%3}, {%4,%5,%6,%7}, {%8,%9}, {%0,%1,%2,%3};"
        : "+f"(c[0]), "+f"(c[1]), "+f"(c[2]), "+f"(c[3])
        : "r"(a[0]), "r"(a[1]), "r"(a[2]), "r"(a[3]), "r"(b0), "r"(b1));
}

// swizzled offset within a 128-row x 32-bf16 (64B/row) tile
__device__ __forceinline__ unsigned sw64(int row, int cb) {
    return (unsigned)(row * 64 + (cb ^ (((row >> 1) & 3) << 4)));
}

// ---------------------------------------------------------------------------
// split fp32 -> bf16 hi + bf16 lo
// ---------------------------------------------------------------------------
__global__ void split_kernel(const float4* __restrict__ x,
                             __nv_bfloat162* __restrict__ hi,
                             __nv_bfloat162* __restrict__ lo, int n4)
{
    int i = blockIdx.x * blockDim.x + threadIdx.x;
    if (i >= n4) return;
    float4 v = x[i];
    __nv_bfloat16 h0 = __float2bfloat16(v.x);
    __nv_bfloat16 h1 = __float2bfloat16(v.y);
    __nv_bfloat16 h2 = __float2bfloat16(v.z);
    __nv_bfloat16 h3 = __float2bfloat16(v.w);
    __nv_bfloat16 l0 = __float2bfloat16(v.x - __bfloat162float(h0));
    __nv_bfloat16 l1 = __float2bfloat16(v.y - __bfloat162float(h1));
    __nv_bfloat16 l2 = __float2bfloat16(v.z - __bfloat162float(h2));
    __nv_bfloat16 l3 = __float2bfloat16(v.w - __bfloat162float(h3));
    hi[2 * i]     = __halves2bfloat162(h0, h1);
    hi[2 * i + 1] = __halves2bfloat162(h2, h3);
    lo[2 * i]     = __halves2bfloat162(l0, l1);
    lo[2 * i + 1] = __halves2bfloat162(l2, l3);
}

// ---------------------------------------------------------------------------
// mma.sync GEMM: C[M,N] = A[M,K] @ B[N,K]^T + bias, via bf16x3 split.
// CTA 128x128, 8 warps (warp tile 64x32), K chunk 32, 3-stage cp.async.
// Stage layout (32 KB): Ah | Al | Bh | Bl, each 128x32 bf16 = 8 KB.
// ---------------------------------------------------------------------------
#define GSTAGE 32768
#define GNSTG  3

__device__ __forceinline__ void gemm_load_stage(
    unsigned sbase, const __nv_bfloat16* a_h, const __nv_bfloat16* a_l,
    const __nv_bfloat16* b_h, const __nv_bfloat16* b_l, int K, int k0, int tid)
{
    const __nv_bfloat16* srcs[4] = {a_h, a_l, b_h, b_l};
#pragma unroll
    for (int j = 0; j < 4; j++) {
        const __nv_bfloat16* g = srcs[j] + k0;
#pragma unroll
        for (int i = 0; i < 2; i++) {
            int slot = i * 256 + tid;          // 0..511
            int row = slot >> 2;
            int cb = (slot & 3) * 16;          // byte offset in 64B row
            cp_async16(sbase + j * 8192 + sw64(row, cb),
                       (const char*)g + (size_t)row * K * 2 + cb);
        }
    }
    CP_COMMIT();
}

__global__ __launch_bounds__(256, 2) void gemm_tc_kernel(
    const __nv_bfloat16* __restrict__ Ah, const __nv_bfloat16* __restrict__ Al,
    const __nv_bfloat16* __restrict__ Bh, const __nv_bfloat16* __restrict__ Bl,
    const float* __restrict__ bias, float* __restrict__ C,
    int M, int N, int K)
{
    extern __shared__ char gsm[];
    const unsigned sm0 = smem_u32(gsm);
    const int tid = threadIdx.x;
    const int w = tid >> 5, lane = tid & 31;
    const int wm = w & 1;          // 2 m-halves of 64 rows
    const int wn = w >> 1;         // 4 n-quarters of 32 cols
    const int bn = blockIdx.x * 128;
    const int bm = blockIdx.y * 128;

    const __nv_bfloat16* a_h = Ah + (size_t)bm * K;
    const __nv_bfloat16* a_l = Al + (size_t)bm * K;
    const __nv_bfloat16* b_h = Bh + (size_t)bn * K;
    const __nv_bfloat16* b_l = Bl + (size_t)bn * K;

    const int nchunks = K >> 5;  // K/32

    float acc[4][4][4];
#pragma unroll
    for (int i = 0; i < 4; i++)
#pragma unroll
        for (int j = 0; j < 4; j++)
#pragma unroll
            for (int q = 0; q < 4; q++) acc[i][j][q] = 0.f;

    // prologue: stages 0,1
    gemm_load_stage(sm0, a_h, a_l, b_h, b_l, K, 0, tid);
    if (nchunks > 1)
        gemm_load_stage(sm0 + GSTAGE, a_h, a_l, b_h, b_l, K, 32, tid);

    for (int c = 0; c < nchunks; c++) {
        if (c + 2 < nchunks) {
            gemm_load_stage(sm0 + ((c + 2) % GNSTG) * GSTAGE,
                            a_h, a_l, b_h, b_l, K, (c + 2) << 5, tid);
            asm volatile("cp.async.wait_group 2;" ::: "memory");
        } else if (c + 1 < nchunks) {
            asm volatile("cp.async.wait_group 1;" ::: "memory");
        } else {
            asm volatile("cp.async.wait_group 0;" ::: "memory");
        }
        __syncthreads();

        const unsigned sbase = sm0 + (c % GNSTG) * GSTAGE;
        const unsigned aoff[3] = {0u, 0u, 8192u};          // Ah, Ah, Al
        const unsigned boff[3] = {16384u, 24576u, 16384u}; // Bh, Bl, Bh
#pragma unroll
        for (int p = 0; p < 3; p++) {
            const unsigned sA = sbase + aoff[p];
            const unsigned sB = sbase + boff[p];
#pragma unroll
            for (int ks = 0; ks < 2; ks++) {
                const int kb = ks * 32;
                // B frags: 2 x ldmatrix.x4 -> 4 n-tiles of 8
                unsigned bf[2][4];
#pragma unroll
                for (int bt = 0; bt < 2; bt++) {
                    int row = wn * 32 + bt * 16 + (lane & 7) + ((lane >> 4) << 3);
                    int cb = kb + (((lane >> 3) & 1) << 4);
                    LDSM_X4(bf[bt], sB + sw64(row, cb));
                }
#pragma unroll
                for (int mt = 0; mt < 4; mt++) {
                    unsigned af[4];
                    {
                        int row = wm * 64 + mt * 16 + (lane & 15);
                        int cb = kb + ((lane >> 4) << 4);
                        LDSM_X4(af, sA + sw64(row, cb));
                    }
#pragma unroll
                    for (int nt = 0; nt < 4; nt++)
                        mma16816(acc[mt][nt], af,
                                 bf[nt >> 1][(nt & 1) * 2],
                                 bf[nt >> 1][(nt & 1) * 2 + 1]);
                }
            }
        }
        __syncthreads();
    }

    // epilogue
    const int gq = lane >> 2, tig = lane & 3;
#pragma unroll
    for (int mt = 0; mt < 4; mt++) {
#pragma unroll
        for (int nt = 0; nt < 4; nt++) {
            int row0 = bm + wm * 64 + mt * 16 + gq;
            int col = bn + wn * 32 + nt * 8 + tig * 2;
            float b0 = bias[col], b1 = bias[col + 1];
            float2 v0 = make_float2(acc[mt][nt][0] + b0, acc[mt][nt][1] + b1);
            float2 v1 = make_float2(acc[mt][nt][2] + b0, acc[mt][nt][3] + b1);
            *(float2*)(C + (size_t)row0 * N + col) = v0;
            *(float2*)(C + (size_t)(row0 + 8) * N + col) = v1;
        }
    }
}

// ---------------------------------------------------------------------------
// RMS norm per 128-dim head chunk. grid (L, 24), block 128.
// ---------------------------------------------------------------------------
__global__ void rms_kernel(const float* __restrict__ X, const float* __restrict__ w,
                           float* __restrict__ Y)
{
    const int row = blockIdx.x;
    const int h = blockIdx.y;
    const int d = threadIdx.x;
    const size_t idx = (size_t)row * HIDW + h * DHW + d;
    float x = X[idx];
    float v = x * x;
#pragma unroll
    for (int off = 16; off > 0; off >>= 1)
        v += __shfl_xor_sync(0xffffffffu, v, off);
    __shared__ float ws[4];
    const int lane = d & 31, wid = d >> 5;
    if (lane == 0) ws[wid] = v;
    __syncthreads();
    float total = ws[0] + ws[1] + ws[2] + ws[3];
    float r = rsqrtf(total * (1.0f / 128.0f) + 1e-6f);
    Y[idx] = x * r * w[d];
}

// ---------------------------------------------------------------------------
// RoPE in place. grid (1536, 24), block 128.
// ---------------------------------------------------------------------------
__global__ void rope_kernel(float* __restrict__ X, const float* __restrict__ cosT,
                            const float* __restrict__ sinT)
{
    __shared__ float sx[128];
    const int row = blockIdx.x;
    const int h = blockIdx.y;
    const int d = threadIdx.x;
    const size_t idx = (size_t)row * HIDW + h * DHW + d;
    float x = X[idx];
    sx[d] = x;
    __syncthreads();
    float c = cosT[row * DHW + d];
    float s = sinT[row * DHW + d];
    float xr = (d & 1) ? sx[d - 1] : -sx[d + 1];
    X[idx] = x * c + xr * s;
}

// ---------------------------------------------------------------------------
// Attention: 8 query rows x 1 head per block, 256 threads.
// smem: q (8*128) | scores (8*nkv)
// ---------------------------------------------------------------------------
__global__ __launch_bounds__(256) void attn_kernel(
    const float* __restrict__ Q, const float* __restrict__ Km,
    const float* __restrict__ Vm, float* __restrict__ O, int nkv)
{
    extern __shared__ float sm[];
    float* sq = sm;            // 1024
    float* ss = sm + 1024;     // 8*nkv

    const int h = blockIdx.y;
    const int r0 = blockIdx.x * 8;
    const int tid = threadIdx.x;

    for (int i = tid; i < 1024; i += 256) {
        int r = i >> 7, d = i & 127;
        sq[i] = Q[(size_t)(r0 + r) * HIDW + h * DHW + d];
    }
    __syncthreads();

    const float scale = 0.08838834764831845f;  // 1/sqrt(128)

    // scores
    for (int k = tid; k < nkv; k += 256) {
        const float4* kr = (const float4*)(Km + (size_t)k * HIDW + h * DHW);
        float acc[8] = {0.f, 0.f, 0.f, 0.f, 0.f, 0.f, 0.f, 0.f};
#pragma unroll 8
        for (int d4 = 0; d4 < 32; d4++) {
            float4 kv = kr[d4];
#pragma unroll
            for (int r = 0; r < 8; r++) {
                float4 qv = ((const float4*)sq)[r * 32 + d4];
                acc[r] += qv.x * kv.x + qv.y * kv.y + qv.z * kv.z + qv.w * kv.w;
            }
        }
#pragma unroll
        for (int r = 0; r < 8; r++) ss[r * nkv + k] = acc[r] * scale;
    }
    __syncthreads();

    // softmax: warp w owns row w (warp-local reductions, no block barriers)
    const int w = tid >> 5, lane = tid & 31;
    float* srow = ss + w * nkv;
    float m = -1e30f;
    for (int k = lane; k < nkv; k += 32) m = fmaxf(m, srow[k]);
#pragma unroll
    for (int off = 16; off > 0; off >>= 1)
        m = fmaxf(m, __shfl_xor_sync(0xffffffffu, m, off));
    float sum = 0.f;
    for (int k = lane; k < nkv; k += 32) {
        float e = __expf(srow[k] - m);
        srow[k] = e;
        sum += e;
    }
#pragma unroll
    for (int off = 16; off > 0; off >>= 1)
        sum += __shfl_xor_sync(0xffffffffu, sum, off);
    const float inv = 1.0f / sum;
    __syncwarp();

    // PV: warp w row w, lane owns float4 chunk 'lane'; 4-way unroll
    float4 a0 = make_float4(0.f, 0.f, 0.f, 0.f);
    float4 a1 = a0, a2 = a0, a3 = a0;
    for (int k = 0; k < nkv; k += 4) {
        float4 s4 = *(const float4*)(srow + k);
        float4 v0 = ((const float4*)(Vm + (size_t)(k + 0) * HIDW + h * DHW))[lane];
        float4 v1 = ((const float4*)(Vm + (size_t)(k + 1) * HIDW + h * DHW))[lane];
        float4 v2 = ((const float4*)(Vm + (size_t)(k + 2) * HIDW + h * DHW))[lane];
        float4 v3 = ((const float4*)(Vm + (size_t)(k + 3) * HIDW + h * DHW))[lane];
        a0.x += s4.x * v0.x; a0.y += s4.x * v0.y; a0.z += s4.x * v0.z; a0.w += s4.x * v0.w;
        a1.x += s4.y * v1.x; a1.y += s4.y * v1.y; a1.z += s4.y * v1.z; a1.w += s4.y * v1.w;
        a2.x += s4.z * v2.x; a2.y += s4.z * v2.y; a2.z += s4.z * v2.z; a2.w += s4.z * v2.w;
        a3.x += s4.w * v3.x; a3.y += s4.w * v3.y; a3.z += s4.w * v3.z; a3.w += s4.w * v3.w;
    }
    float4 r;
    r.x = ((a0.x + a1.x) + (a2.x + a3.x)) * inv;
    r.y = ((a0.y + a1.y) + (a2.y + a3.y)) * inv;
    r.z = ((a0.z + a1.z) + (a2.z + a3.z)) * inv;
    r.w = ((a0.w + a1.w) + (a2.w + a3.w)) * inv;
    ((float4*)(O + (size_t)(r0 + w) * HIDW + h * DHW))[lane] = r;
}

// ---------------------------------------------------------------------------
// img += ip_out * mask  (BBOX = (8,8,24,24) on 32x32 grid)
// ---------------------------------------------------------------------------
__global__ void maskadd_kernel(float* __restrict__ A, const float* __restrict__ IP)
{
    const int i = blockIdx.x;
    const int y = i >> 5, x = i & 31;
    if (y < 8 || y >= 24 || x < 8 || x >= 24) return;
    for (int c = threadIdx.x; c < HIDW; c += 256)
        A[(size_t)i * HIDW + c] += IP[(size_t)i * HIDW + c];
}

// ---------------------------------------------------------------------------
extern "C" void kernel_launch(void* const* d_in, const int* in_sizes, int n_in,
                              void* d_out, int out_size)
{
    const float* hs    = (const float*)d_in[0];
    const float* enc   = (const float*)d_in[1];
    const float* ip    = (const float*)d_in[2];
    const float* cosT  = (const float*)d_in[3];
    const float* sinT  = (const float*)d_in[4];
    const float* bq    = (const float*)d_in[6];
    const float* bk    = (const float*)d_in[8];
    const float* bv    = (const float*)d_in[10];
    const float* nqw   = (const float*)d_in[11];
    const float* nkw   = (const float*)d_in[12];
    const float* bqa   = (const float*)d_in[14];
    const float* bka   = (const float*)d_in[16];
    const float* bva   = (const float*)d_in[18];
    const float* naqw  = (const float*)d_in[19];
    const float* nakw  = (const float*)d_in[20];
    const float* bout  = (const float*)d_in[22];
    const float* baout = (const float*)d_in[24];
    const float* bkip  = (const float*)d_in[26];
    const float* bvip  = (const float*)d_in[28];
    const float* nipq  = (const float*)d_in[29];
    const float* nipk  = (const float*)d_in[30];

    float* buf = nullptr;
    cudaGetSymbolAddress((void**)&buf, g_buf);
    __nv_bfloat16* bh = nullptr;
    __nv_bfloat16* bl = nullptr;
    cudaGetSymbolAddress((void**)&bh, g_bh);
    cudaGetSymbolAddress((void**)&bl, g_bl);

    float* Qb   = buf + (size_t)O_Q * HIDW;
    float* Kb   = buf + (size_t)O_K * HIDW;
    float* EQb  = buf + (size_t)O_EQ * HIDW;
    float* EKb  = buf + (size_t)O_EK * HIDW;
    float* IPKb = buf + (size_t)O_IPK * HIDW;
    float* IPVb = buf + (size_t)O_IPV * HIDW;
    float* IPQb = buf + (size_t)O_IPQ * HIDW;
    float* QFb  = buf + (size_t)O_QF * HIDW;
    float* KFb  = buf + (size_t)O_KF * HIDW;
    float* VFb  = buf + (size_t)O_VF * HIDW;
    float* ATb  = buf + (size_t)O_ATTN * HIDW;
    float* IPOb = buf + (size_t)O_IPOUT * HIDW;

    float* out_img = (float*)d_out;
    float* out_enc = (float*)d_out + (size_t)IMGN * HIDW;

    const int smem_gemm = GNSTG * GSTAGE;                 // 98304
    const int smem_main = (1024 + 8 * S_ALL) * 4;         // 53248
    const int smem_ip   = (1024 + 8 * 128) * 4;
    cudaFuncSetAttribute(gemm_tc_kernel, cudaFuncAttributeMaxDynamicSharedMemorySize,
                         smem_gemm);
    cudaFuncSetAttribute(attn_kernel, cudaFuncAttributeMaxDynamicSharedMemorySize,
                         smem_main);

    dim3 blk(256);

    // --- split inputs (weights + activations) to bf16 hi/lo ---
    struct SplitJob { const float* src; size_t off; size_t n; };
    const SplitJob jobs[13] = {
        {(const float*)d_in[5],  OFF_WQ,    9437184ull},
        {(const float*)d_in[7],  OFF_WK,    9437184ull},
        {(const float*)d_in[9],  OFF_WV,    9437184ull},
        {(const float*)d_in[13], OFF_WQA,   9437184ull},
        {(const float*)d_in[15], OFF_WKA,   9437184ull},
        {(const float*)d_in[17], OFF_WVA,   9437184ull},
        {(const float*)d_in[21], OFF_WOUT,  9437184ull},
        {(const float*)d_in[23], OFF_WAOUT, 9437184ull},
        {(const float*)d_in[25], OFF_WKIP,  3538944ull},
        {(const float*)d_in[27], OFF_WVIP,  3538944ull},
        {hs,  OFF_HS,  3145728ull},
        {enc, OFF_ENC, 1572864ull},
        {ip,  OFF_IP,  147456ull},
    };
    for (int j = 0; j < 13; j++) {
        int n4 = (int)(jobs[j].n / 4);
        split_kernel<<<(n4 + 255) / 256, 256>>>(
            (const float4*)jobs[j].src,
            (__nv_bfloat162*)(bh + jobs[j].off),
            (__nv_bfloat162*)(bl + jobs[j].off), n4);
    }

    // --- projections via mma.sync tensor cores ---
#define GEMM_TC(offA, offB, bias, C, M, K) \
    gemm_tc_kernel<<<dim3(HIDW / 128, (M) / 128), blk, smem_gemm>>>( \
        bh + (offA), bl + (offA), bh + (offB), bl + (offB), bias, C, M, HIDW, K)

    GEMM_TC(OFF_HS, OFF_WQ, bq, Qb, IMGN, HIDW);
    GEMM_TC(OFF_HS, OFF_WK, bk, Kb, IMGN, HIDW);
    GEMM_TC(OFF_HS, OFF_WV, bv, VFb + (size_t)TXTN * HIDW, IMGN, HIDW);
    GEMM_TC(OFF_ENC, OFF_WQA, bqa, EQb, TXTN, HIDW);
    GEMM_TC(OFF_ENC, OFF_WKA, bka, EKb, TXTN, HIDW);
    GEMM_TC(OFF_ENC, OFF_WVA, bva, VFb, TXTN, HIDW);
    GEMM_TC(OFF_IP, OFF_WKIP, bkip, IPKb, 128, 1152);
    GEMM_TC(OFF_IP, OFF_WVIP, bvip, IPVb, 128, 1152);

    // --- RMS norms ---
    rms_kernel<<<dim3(IMGN, NHW), 128>>>(Qb, nipq, IPQb);
    rms_kernel<<<dim3(128, NHW), 128>>>(IPKb, nipk, IPKb);
    rms_kernel<<<dim3(IMGN, NHW), 128>>>(Qb, nqw, QFb + (size_t)TXTN * HIDW);
    rms_kernel<<<dim3(IMGN, NHW), 128>>>(Kb, nkw, KFb + (size_t)TXTN * HIDW);
    rms_kernel<<<dim3(TXTN, NHW), 128>>>(EQb, naqw, QFb);
    rms_kernel<<<dim3(TXTN, NHW), 128>>>(EKb, nakw, KFb);

    // --- RoPE ---
    rope_kernel<<<dim3(S_ALL, NHW), 128>>>(QFb, cosT, sinT);
    rope_kernel<<<dim3(S_ALL, NHW), 128>>>(KFb, cosT, sinT);

    // --- attention ---
    attn_kernel<<<dim3(S_ALL / 8, NHW), blk, smem_main>>>(QFb, KFb, VFb, ATb, S_ALL);
    attn_kernel<<<dim3(IMGN / 8, NHW), blk, smem_ip>>>(IPQb, IPKb, IPVb, IPOb, 128);

    // --- mask add on img part ---
    maskadd_kernel<<<IMGN, blk>>>(ATb + (size_t)TXTN * HIDW, IPOb);

    // --- split attention outputs, then output projections ---
    {
        int n4 = (int)(3145728ull / 4);
        split_kernel<<<(n4 + 255) / 256, 256>>>(
            (const float4*)(ATb + (size_t)TXTN * HIDW),
            (__nv_bfloat162*)(bh + OFF_ATI), (__nv_bfloat162*)(bl + OFF_ATI), n4);
        n4 = (int)(1572864ull / 4);
        split_kernel<<<(n4 + 255) / 256, 256>>>(
            (const float4*)ATb,
            (__nv_bfloat162*)(bh + OFF_ATE), (__nv_bfloat162*)(bl + OFF_ATE), n4);
    }
    GEMM_TC(OFF_ATI, OFF_WOUT, bout, out_img, IMGN, HIDW);
    GEMM_TC(OFF_ATE, OFF_WAOUT, baout, out_enc, TXTN, HIDW);
#undef GEMM_TC
}

// round 7
// speedup vs baseline: 6.7485x; 2.3519x over previous
#include <cuda_runtime.h>
#include <cuda_bf16.h>

#define HIDW 3072
#define DHW  128
#define NHW  24
#define S_ALL 1536
#define TXTN 512
#define IMGN 1024

// fp32 scratch (intermediates)
__device__ float g_buf[11520ull * 3072ull];

#define O_Q     0
#define O_K     1024
#define O_EQ    2048
#define O_EK    2560
#define O_IPK   3072
#define O_IPV   3200
#define O_IPQ   3328
#define O_QF    4352
#define O_KF    5888
#define O_VF    7424
#define O_ATTN  8960
#define O_IPOUT 10496

// bf16 hi/lo arenas (weights + activations), element offsets below
#define BF_TOT 110250000ull
__device__ __nv_bfloat16 g_bh[BF_TOT];
__device__ __nv_bfloat16 g_bl[BF_TOT];

#define OFF_WQ    0ull
#define OFF_WK    9437184ull
#define OFF_WV    18874368ull
#define OFF_WQA   28311552ull
#define OFF_WKA   37748736ull
#define OFF_WVA   47185920ull
#define OFF_WOUT  56623104ull
#define OFF_WAOUT 66060288ull
#define OFF_WKIP  75497472ull
#define OFF_WVIP  79036416ull
#define OFF_HS    82575360ull
#define OFF_ENC   85721088ull
#define OFF_IP    87293952ull
#define OFF_ATI   87441408ull
#define OFF_ATE   90587136ull
#define OFF_QF    92160000ull
#define OFF_KF    96878592ull
#define OFF_VF    101597184ull
#define OFF_IPQ   106315776ull
#define OFF_IPK   109461504ull
#define OFF_IPV   109854720ull

// ---------------------------------------------------------------------------
// PTX helpers (plain sm_103-compatible: cp.async, ldmatrix, mma.sync)
// ---------------------------------------------------------------------------
__device__ __forceinline__ unsigned smem_u32(const void* p) {
    return (unsigned)__cvta_generic_to_shared(p);
}
__device__ __forceinline__ void cp_async16(unsigned s, const void* g) {
    asm volatile("cp.async.cg.shared.global [%0], [%1], 16;" :: "r"(s), "l"(g));
}
#define CP_COMMIT() asm volatile("cp.async.commit_group;" ::: "memory")

#define LDSM_X4(r, addr) \
    asm volatile("ldmatrix.sync.aligned.m8n8.x4.shared.b16 {%0,%1,%2,%3}, [%4];" \
                 : "=r"((r)[0]), "=r"((r)[1]), "=r"((r)[2]), "=r"((r)[3]) \
                 : "r"(addr))
#define LDSM_X4T(r, addr) \
    asm volatile("ldmatrix.sync.aligned.m8n8.x4.trans.shared.b16 {%0,%1,%2,%3}, [%4];" \
                 : "=r"((r)[0]), "=r"((r)[1]), "=r"((r)[2]), "=r"((r)[3]) \
                 : "r"(addr))

__device__ __forceinline__ void mma16816(float* c, const unsigned* a,
                                         unsigned b0, unsigned b1) {
    asm volatile(
        "mma.sync.aligned.m16n8k16.row.col.f32.bf16.bf16.f32 "
        "{%0,%1,%2,%3}, {%4,%5,%6,%7}, {%8,%9}, {%0,%1,%2,%3};"
        : "+f"(c[0]), "+f"(c[1]), "+f"(c[2]), "+f"(c[3])
        : "r"(a[0]), "r"(a[1]), "r"(a[2]), "r"(a[3]), "r"(b0), "r"(b1));
}

__device__ __forceinline__ float fex2(float x) {
    float y;
    asm("ex2.approx.f32 %0, %1;" : "=f"(y) : "f"(x));
    return y;
}
__device__ __forceinline__ unsigned pack_bf2(float lo, float hi) {
    unsigned r;
    asm("cvt.rn.bf16x2.f32 %0, %1, %2;" : "=r"(r) : "f"(hi), "f"(lo));
    return r;
}

// swizzled offset within a 64B-row tile (32 bf16 per row)
__device__ __forceinline__ unsigned sw64(int row, int cb) {
    return (unsigned)(row * 64 + (cb ^ (((row >> 1) & 3) << 4)));
}
// swizzled offset within a 256B-row tile (128 bf16 per row)
__device__ __forceinline__ unsigned sw256(int row, int cb) {
    return (unsigned)(row * 256 + (cb ^ ((row & 7) << 4)));
}

// ---------------------------------------------------------------------------
// split fp32 -> bf16 hi + bf16 lo
// ---------------------------------------------------------------------------
__global__ void split_kernel(const float4* __restrict__ x,
                             __nv_bfloat162* __restrict__ hi,
                             __nv_bfloat162* __restrict__ lo, int n4)
{
    int i = blockIdx.x * blockDim.x + threadIdx.x;
    if (i >= n4) return;
    float4 v = x[i];
    __nv_bfloat16 h0 = __float2bfloat16(v.x);
    __nv_bfloat16 h1 = __float2bfloat16(v.y);
    __nv_bfloat16 h2 = __float2bfloat16(v.z);
    __nv_bfloat16 h3 = __float2bfloat16(v.w);
    __nv_bfloat16 l0 = __float2bfloat16(v.x - __bfloat162float(h0));
    __nv_bfloat16 l1 = __float2bfloat16(v.y - __bfloat162float(h1));
    __nv_bfloat16 l2 = __float2bfloat16(v.z - __bfloat162float(h2));
    __nv_bfloat16 l3 = __float2bfloat16(v.w - __bfloat162float(h3));
    hi[2 * i]     = __halves2bfloat162(h0, h1);
    hi[2 * i + 1] = __halves2bfloat162(h2, h3);
    lo[2 * i]     = __halves2bfloat162(l0, l1);
    lo[2 * i + 1] = __halves2bfloat162(l2, l3);
}

// ---------------------------------------------------------------------------
// mma.sync GEMM: C[M,N] = A[M,K] @ B[N,K]^T + bias, via bf16x3 split.
// CTA 128x128, 8 warps (warp tile 64x32), K chunk 32, 3-stage cp.async.
// ---------------------------------------------------------------------------
#define GSTAGE 32768
#define GNSTG  3

__device__ __forceinline__ void gemm_load_stage(
    unsigned sbase, const __nv_bfloat16* a_h, const __nv_bfloat16* a_l,
    const __nv_bfloat16* b_h, const __nv_bfloat16* b_l, int K, int k0, int tid)
{
    const __nv_bfloat16* srcs[4] = {a_h, a_l, b_h, b_l};
#pragma unroll
    for (int j = 0; j < 4; j++) {
        const __nv_bfloat16* g = srcs[j] + k0;
#pragma unroll
        for (int i = 0; i < 2; i++) {
            int slot = i * 256 + tid;          // 0..511
            int row = slot >> 2;
            int cb = (slot & 3) * 16;          // byte offset in 64B row
            cp_async16(sbase + j * 8192 + sw64(row, cb),
                       (const char*)g + (size_t)row * K * 2 + cb);
        }
    }
    CP_COMMIT();
}

__global__ __launch_bounds__(256, 2) void gemm_tc_kernel(
    const __nv_bfloat16* __restrict__ Ah, const __nv_bfloat16* __restrict__ Al,
    const __nv_bfloat16* __restrict__ Bh, const __nv_bfloat16* __restrict__ Bl,
    const float* __restrict__ bias, float* __restrict__ C,
    int M, int N, int K)
{
    extern __shared__ char gsm[];
    const unsigned sm0 = smem_u32(gsm);
    const int tid = threadIdx.x;
    const int w = tid >> 5, lane = tid & 31;
    const int wm = w & 1;          // 2 m-halves of 64 rows
    const int wn = w >> 1;         // 4 n-quarters of 32 cols
    const int bn = blockIdx.x * 128;
    const int bm = blockIdx.y * 128;

    const __nv_bfloat16* a_h = Ah + (size_t)bm * K;
    const __nv_bfloat16* a_l = Al + (size_t)bm * K;
    const __nv_bfloat16* b_h = Bh + (size_t)bn * K;
    const __nv_bfloat16* b_l = Bl + (size_t)bn * K;

    const int nchunks = K >> 5;  // K/32

    float acc[4][4][4];
#pragma unroll
    for (int i = 0; i < 4; i++)
#pragma unroll
        for (int j = 0; j < 4; j++)
#pragma unroll
            for (int q = 0; q < 4; q++) acc[i][j][q] = 0.f;

    gemm_load_stage(sm0, a_h, a_l, b_h, b_l, K, 0, tid);
    if (nchunks > 1)
        gemm_load_stage(sm0 + GSTAGE, a_h, a_l, b_h, b_l, K, 32, tid);

    for (int c = 0; c < nchunks; c++) {
        if (c + 2 < nchunks) {
            gemm_load_stage(sm0 + ((c + 2) % GNSTG) * GSTAGE,
                            a_h, a_l, b_h, b_l, K, (c + 2) << 5, tid);
            asm volatile("cp.async.wait_group 2;" ::: "memory");
        } else if (c + 1 < nchunks) {
            asm volatile("cp.async.wait_group 1;" ::: "memory");
        } else {
            asm volatile("cp.async.wait_group 0;" ::: "memory");
        }
        __syncthreads();

        const unsigned sbase = sm0 + (c % GNSTG) * GSTAGE;
        const unsigned aoff[3] = {0u, 0u, 8192u};          // Ah, Ah, Al
        const unsigned boff[3] = {16384u, 24576u, 16384u}; // Bh, Bl, Bh
#pragma unroll
        for (int p = 0; p < 3; p++) {
            const unsigned sA = sbase + aoff[p];
            const unsigned sB = sbase + boff[p];
#pragma unroll
            for (int ks = 0; ks < 2; ks++) {
                const int kb = ks * 32;
                unsigned bf[2][4];
#pragma unroll
                for (int bt = 0; bt < 2; bt++) {
                    int row = wn * 32 + bt * 16 + (lane & 7) + ((lane >> 4) << 3);
                    int cb = kb + (((lane >> 3) & 1) << 4);
                    LDSM_X4(bf[bt], sB + sw64(row, cb));
                }
#pragma unroll
                for (int mt = 0; mt < 4; mt++) {
                    unsigned af[4];
                    {
                        int row = wm * 64 + mt * 16 + (lane & 15);
                        int cb = kb + ((lane >> 4) << 4);
                        LDSM_X4(af, sA + sw64(row, cb));
                    }
#pragma unroll
                    for (int nt = 0; nt < 4; nt++)
                        mma16816(acc[mt][nt], af,
                                 bf[nt >> 1][(nt & 1) * 2],
                                 bf[nt >> 1][(nt & 1) * 2 + 1]);
                }
            }
        }
        __syncthreads();
    }

    const int gq = lane >> 2, tig = lane & 3;
#pragma unroll
    for (int mt = 0; mt < 4; mt++) {
#pragma unroll
        for (int nt = 0; nt < 4; nt++) {
            int row0 = bm + wm * 64 + mt * 16 + gq;
            int col = bn + wn * 32 + nt * 8 + tig * 2;
            float b0 = bias[col], b1 = bias[col + 1];
            float2 v0 = make_float2(acc[mt][nt][0] + b0, acc[mt][nt][1] + b1);
            float2 v1 = make_float2(acc[mt][nt][2] + b0, acc[mt][nt][3] + b1);
            *(float2*)(C + (size_t)row0 * N + col) = v0;
            *(float2*)(C + (size_t)(row0 + 8) * N + col) = v1;
        }
    }
}

// ---------------------------------------------------------------------------
// Flash attention on mma.sync with bf16 hi/lo 3-pass.
// Block: 128 q rows x 1 head, 256 threads (8 warps x 16 rows).
// K/V tiles of 64 kv, double-buffered cp.async.
// smem: Qh(32K) Ql(32K) | stage{0,1}: Kh Kl Vh Vl (16K each) = 192 KB.
// ---------------------------------------------------------------------------
#define SCL2E 0.12751743f   // (1/sqrt(128)) * log2(e)

__device__ __forceinline__ void fa_load_stage(
    unsigned sb, const char* kh, const char* kl, const char* vh, const char* vl,
    int kv0, size_t hb, int tid)
{
    const char* srcs[4] = {kh, kl, vh, vl};
#pragma unroll
    for (int j = 0; j < 4; j++) {
#pragma unroll
        for (int i = 0; i < 4; i++) {
            int slot = i * 256 + tid;    // 0..1023
            int row = slot >> 4, cb = (slot & 15) * 16;
            cp_async16(sb + j * 16384 + sw256(row, cb),
                       srcs[j] + (size_t)(kv0 + row) * 6144 + hb + cb);
        }
    }
    CP_COMMIT();
}

__global__ __launch_bounds__(256, 1) void flash_kernel(
    const __nv_bfloat16* __restrict__ Qh, const __nv_bfloat16* __restrict__ Ql,
    const __nv_bfloat16* __restrict__ Kh, const __nv_bfloat16* __restrict__ Kl,
    const __nv_bfloat16* __restrict__ Vh, const __nv_bfloat16* __restrict__ Vl,
    float* __restrict__ O, int nkv)
{
    extern __shared__ char fsm[];
    const unsigned sQh = smem_u32(fsm);
    const unsigned sQl = sQh + 32768;
    const unsigned sStg = sQh + 65536;
    const int tid = threadIdx.x;
    const int w = tid >> 5, lane = tid & 31;
    const int gp = lane >> 2, tig = lane & 3;
    const int h = blockIdx.y;
    const int q0 = blockIdx.x * 128;
    const int m0 = w * 16;
    const size_t hb = (size_t)h * 256;   // byte offset of head within 6144B row

    // Q tiles (hi, lo): 128 rows x 256B each
    {
        const char* gq[2] = {(const char*)Qh, (const char*)Ql};
        const unsigned sq[2] = {sQh, sQl};
#pragma unroll
        for (int t2 = 0; t2 < 2; t2++)
#pragma unroll
            for (int i = 0; i < 8; i++) {
                int slot = i * 256 + tid;   // 0..2047
                int row = slot >> 4, cb = (slot & 15) * 16;
                cp_async16(sq[t2] + sw256(row, cb),
                           gq[t2] + (size_t)(q0 + row) * 6144 + hb + cb);
            }
        CP_COMMIT();
    }

    const int ntile = nkv >> 6;
    fa_load_stage(sStg, (const char*)Kh, (const char*)Kl,
                  (const char*)Vh, (const char*)Vl, 0, hb, tid);

    float o[16][4];
#pragma unroll
    for (int i = 0; i < 16; i++)
#pragma unroll
        for (int j = 0; j < 4; j++) o[i][j] = 0.f;
    float m_0 = -1e30f, m_1 = -1e30f;
    float l_0 = 0.f, l_1 = 0.f;

    for (int t = 0; t < ntile; t++) {
        if (t + 1 < ntile) {
            fa_load_stage(sStg + ((t + 1) & 1) * 65536, (const char*)Kh,
                          (const char*)Kl, (const char*)Vh, (const char*)Vl,
                          (t + 1) * 64, hb, tid);
            asm volatile("cp.async.wait_group 1;" ::: "memory");
        } else {
            asm volatile("cp.async.wait_group 0;" ::: "memory");
        }
        __syncthreads();

        const unsigned sb = sStg + (t & 1) * 65536;
        const unsigned sK_h = sb, sK_l = sb + 16384;
        const unsigned sV_h = sb + 32768, sV_l = sb + 49152;

        // ---- scores S = Q.K^T (3 passes hi/lo) ----
        float s[8][4];
#pragma unroll
        for (int i = 0; i < 8; i++)
#pragma unroll
            for (int j = 0; j < 4; j++) s[i][j] = 0.f;

#pragma unroll
        for (int kc = 0; kc < 8; kc++) {
            const int arow = m0 + (lane & 15);
            const int acb = kc * 32 + ((lane >> 4) << 4);
            unsigned afh[4], afl[4];
            LDSM_X4(afh, sQh + sw256(arow, acb));
            LDSM_X4(afl, sQl + sw256(arow, acb));
            const int brow = (lane & 7) + ((lane >> 4) << 3);
            const int bcb = kc * 32 + (((lane >> 3) & 1) << 4);
#pragma unroll
            for (int bt = 0; bt < 4; bt++) {
                unsigned bh_[4], bl_[4];
                LDSM_X4(bh_, sK_h + sw256(bt * 16 + brow, bcb));
                LDSM_X4(bl_, sK_l + sw256(bt * 16 + brow, bcb));
                mma16816(s[2 * bt], afh, bh_[0], bh_[1]);
                mma16816(s[2 * bt + 1], afh, bh_[2], bh_[3]);
                mma16816(s[2 * bt], afh, bl_[0], bl_[1]);
                mma16816(s[2 * bt + 1], afh, bl_[2], bl_[3]);
                mma16816(s[2 * bt], afl, bh_[0], bh_[1]);
                mma16816(s[2 * bt + 1], afl, bh_[2], bh_[3]);
            }
        }

        // ---- online softmax (warp-local; rows gp and gp+8) ----
        float mx0 = -1e30f, mx1 = -1e30f;
#pragma unroll
        for (int nt = 0; nt < 8; nt++) {
            mx0 = fmaxf(mx0, fmaxf(s[nt][0], s[nt][1]));
            mx1 = fmaxf(mx1, fmaxf(s[nt][2], s[nt][3]));
        }
        mx0 = fmaxf(mx0, __shfl_xor_sync(0xffffffffu, mx0, 1));
        mx0 = fmaxf(mx0, __shfl_xor_sync(0xffffffffu, mx0, 2));
        mx1 = fmaxf(mx1, __shfl_xor_sync(0xffffffffu, mx1, 1));
        mx1 = fmaxf(mx1, __shfl_xor_sync(0xffffffffu, mx1, 2));
        const float mn0 = fmaxf(m_0, mx0), mn1 = fmaxf(m_1, mx1);
        const float al0 = fex2((m_0 - mn0) * SCL2E);
        const float al1 = fex2((m_1 - mn1) * SCL2E);
        m_0 = mn0; m_1 = mn1;

        float sum0 = 0.f, sum1 = 0.f;
        unsigned aPh[4][4], aPl[4][4];
#pragma unroll
        for (int nt = 0; nt < 8; nt++) {
            float p0 = fex2((s[nt][0] - mn0) * SCL2E);
            float p1 = fex2((s[nt][1] - mn0) * SCL2E);
            float p2 = fex2((s[nt][2] - mn1) * SCL2E);
            float p3 = fex2((s[nt][3] - mn1) * SCL2E);
            sum0 += p0 + p1;
            sum1 += p2 + p3;
            float h0 = __bfloat162float(__float2bfloat16(p0));
            float h1 = __bfloat162float(__float2bfloat16(p1));
            float h2 = __bfloat162float(__float2bfloat16(p2));
            float h3 = __bfloat162float(__float2bfloat16(p3));
            const int kc = nt >> 1, hf = (nt & 1) * 2;
            aPh[kc][hf] = pack_bf2(p0, p1);
            aPh[kc][hf + 1] = pack_bf2(p2, p3);
            aPl[kc][hf] = pack_bf2(p0 - h0, p1 - h1);
            aPl[kc][hf + 1] = pack_bf2(p2 - h2, p3 - h3);
        }
        sum0 += __shfl_xor_sync(0xffffffffu, sum0, 1);
        sum0 += __shfl_xor_sync(0xffffffffu, sum0, 2);
        sum1 += __shfl_xor_sync(0xffffffffu, sum1, 1);
        sum1 += __shfl_xor_sync(0xffffffffu, sum1, 2);
        l_0 = l_0 * al0 + sum0;
        l_1 = l_1 * al1 + sum1;

        // rescale O
#pragma unroll
        for (int i = 0; i < 16; i++) {
            o[i][0] *= al0; o[i][1] *= al0;
            o[i][2] *= al1; o[i][3] *= al1;
        }

        // ---- PV: O += P.V (3 passes) ----
        const int vrow0 = (lane & 7) + (((lane >> 3) & 1) << 3);
        const int vcbl = (lane >> 4) << 4;
#pragma unroll
        for (int kc = 0; kc < 4; kc++) {
            const int vr = kc * 16 + vrow0;
#pragma unroll
            for (int nb = 0; nb < 8; nb++) {
                unsigned vh_[4], vl_[4];
                const int vcb = nb * 32 + vcbl;
                LDSM_X4T(vh_, sV_h + sw256(vr, vcb));
                LDSM_X4T(vl_, sV_l + sw256(vr, vcb));
                mma16816(o[2 * nb], aPh[kc], vh_[0], vh_[1]);
                mma16816(o[2 * nb + 1], aPh[kc], vh_[2], vh_[3]);
                mma16816(o[2 * nb], aPh[kc], vl_[0], vl_[1]);
                mma16816(o[2 * nb + 1], aPh[kc], vl_[2], vl_[3]);
                mma16816(o[2 * nb], aPl[kc], vh_[0], vh_[1]);
                mma16816(o[2 * nb + 1], aPl[kc], vh_[2], vh_[3]);
            }
        }
        __syncthreads();
    }

    // ---- normalize + store ----
    const float inv0 = 1.0f / l_0, inv1 = 1.0f / l_1;
    const int row0 = q0 + m0 + gp;
#pragma unroll
    for (int nt = 0; nt < 16; nt++) {
        const int col = h * 128 + nt * 8 + tig * 2;
        *(float2*)(O + (size_t)row0 * HIDW + col) =
            make_float2(o[nt][0] * inv0, o[nt][1] * inv0);
        *(float2*)(O + (size_t)(row0 + 8) * HIDW + col) =
            make_float2(o[nt][2] * inv1, o[nt][3] * inv1);
    }
}

// ---------------------------------------------------------------------------
// RMS norm per 128-dim head chunk. grid (L, 24), block 128.
// ---------------------------------------------------------------------------
__global__ void rms_kernel(const float* __restrict__ X, const float* __restrict__ w,
                           float* __restrict__ Y)
{
    const int row = blockIdx.x;
    const int h = blockIdx.y;
    const int d = threadIdx.x;
    const size_t idx = (size_t)row * HIDW + h * DHW + d;
    float x = X[idx];
    float v = x * x;
#pragma unroll
    for (int off = 16; off > 0; off >>= 1)
        v += __shfl_xor_sync(0xffffffffu, v, off);
    __shared__ float ws[4];
    const int lane = d & 31, wid = d >> 5;
    if (lane == 0) ws[wid] = v;
    __syncthreads();
    float total = ws[0] + ws[1] + ws[2] + ws[3];
    float r = rsqrtf(total * (1.0f / 128.0f) + 1e-6f);
    Y[idx] = x * r * w[d];
}

// ---------------------------------------------------------------------------
// RoPE in place. grid (1536, 24), block 128.
// ---------------------------------------------------------------------------
__global__ void rope_kernel(float* __restrict__ X, const float* __restrict__ cosT,
                            const float* __restrict__ sinT)
{
    __shared__ float sx[128];
    const int row = blockIdx.x;
    const int h = blockIdx.y;
    const int d = threadIdx.x;
    const size_t idx = (size_t)row * HIDW + h * DHW + d;
    float x = X[idx];
    sx[d] = x;
    __syncthreads();
    float c = cosT[row * DHW + d];
    float s = sinT[row * DHW + d];
    float xr = (d & 1) ? sx[d - 1] : -sx[d + 1];
    X[idx] = x * c + xr * s;
}

// ---------------------------------------------------------------------------
// img += ip_out * mask  (BBOX = (8,8,24,24) on 32x32 grid)
// ---------------------------------------------------------------------------
__global__ void maskadd_kernel(float* __restrict__ A, const float* __restrict__ IP)
{
    const int i = blockIdx.x;
    const int y = i >> 5, x = i & 31;
    if (y < 8 || y >= 24 || x < 8 || x >= 24) return;
    for (int c = threadIdx.x; c < HIDW; c += 256)
        A[(size_t)i * HIDW + c] += IP[(size_t)i * HIDW + c];
}

// ---------------------------------------------------------------------------
extern "C" void kernel_launch(void* const* d_in, const int* in_sizes, int n_in,
                              void* d_out, int out_size)
{
    const float* hs    = (const float*)d_in[0];
    const float* enc   = (const float*)d_in[1];
    const float* ip    = (const float*)d_in[2];
    const float* cosT  = (const float*)d_in[3];
    const float* sinT  = (const float*)d_in[4];
    const float* bq    = (const float*)d_in[6];
    const float* bk    = (const float*)d_in[8];
    const float* bv    = (const float*)d_in[10];
    const float* nqw   = (const float*)d_in[11];
    const float* nkw   = (const float*)d_in[12];
    const float* bqa   = (const float*)d_in[14];
    const float* bka   = (const float*)d_in[16];
    const float* bva   = (const float*)d_in[18];
    const float* naqw  = (const float*)d_in[19];
    const float* nakw  = (const float*)d_in[20];
    const float* bout  = (const float*)d_in[22];
    const float* baout = (const float*)d_in[24];
    const float* bkip  = (const float*)d_in[26];
    const float* bvip  = (const float*)d_in[28];
    const float* nipq  = (const float*)d_in[29];
    const float* nipk  = (const float*)d_in[30];

    float* buf = nullptr;
    cudaGetSymbolAddress((void**)&buf, g_buf);
    __nv_bfloat16* bh = nullptr;
    __nv_bfloat16* bl = nullptr;
    cudaGetSymbolAddress((void**)&bh, g_bh);
    cudaGetSymbolAddress((void**)&bl, g_bl);

    float* Qb   = buf + (size_t)O_Q * HIDW;
    float* Kb   = buf + (size_t)O_K * HIDW;
    float* EQb  = buf + (size_t)O_EQ * HIDW;
    float* EKb  = buf + (size_t)O_EK * HIDW;
    float* IPKb = buf + (size_t)O_IPK * HIDW;
    float* IPVb = buf + (size_t)O_IPV * HIDW;
    float* IPQb = buf + (size_t)O_IPQ * HIDW;
    float* QFb  = buf + (size_t)O_QF * HIDW;
    float* KFb  = buf + (size_t)O_KF * HIDW;
    float* VFb  = buf + (size_t)O_VF * HIDW;
    float* ATb  = buf + (size_t)O_ATTN * HIDW;
    float* IPOb = buf + (size_t)O_IPOUT * HIDW;

    float* out_img = (float*)d_out;
    float* out_enc = (float*)d_out + (size_t)IMGN * HIDW;

    const int smem_gemm = GNSTG * GSTAGE;       // 98304
    const int smem_fa   = 196608;
    cudaFuncSetAttribute(gemm_tc_kernel, cudaFuncAttributeMaxDynamicSharedMemorySize,
                         smem_gemm);
    cudaFuncSetAttribute(flash_kernel, cudaFuncAttributeMaxDynamicSharedMemorySize,
                         smem_fa);

    dim3 blk(256);

    // --- split inputs (weights + activations) to bf16 hi/lo ---
    struct SplitJob { const float* src; size_t off; size_t n; };
    const SplitJob jobs[13] = {
        {(const float*)d_in[5],  OFF_WQ,    9437184ull},
        {(const float*)d_in[7],  OFF_WK,    9437184ull},
        {(const float*)d_in[9],  OFF_WV,    9437184ull},
        {(const float*)d_in[13], OFF_WQA,   9437184ull},
        {(const float*)d_in[15], OFF_WKA,   9437184ull},
        {(const float*)d_in[17], OFF_WVA,   9437184ull},
        {(const float*)d_in[21], OFF_WOUT,  9437184ull},
        {(const float*)d_in[23], OFF_WAOUT, 9437184ull},
        {(const float*)d_in[25], OFF_WKIP,  3538944ull},
        {(const float*)d_in[27], OFF_WVIP,  3538944ull},
        {hs,  OFF_HS,  3145728ull},
        {enc, OFF_ENC, 1572864ull},
        {ip,  OFF_IP,  147456ull},
    };
    for (int j = 0; j < 13; j++) {
        int n4 = (int)(jobs[j].n / 4);
        split_kernel<<<(n4 + 255) / 256, 256>>>(
            (const float4*)jobs[j].src,
            (__nv_bfloat162*)(bh + jobs[j].off),
            (__nv_bfloat162*)(bl + jobs[j].off), n4);
    }

    // --- projections via mma.sync tensor cores ---
#define GEMM_TC(offA, offB, bias, C, M, K) \
    gemm_tc_kernel<<<dim3(HIDW / 128, (M) / 128), blk, smem_gemm>>>( \
        bh + (offA), bl + (offA), bh + (offB), bl + (offB), bias, C, M, HIDW, K)

    GEMM_TC(OFF_HS, OFF_WQ, bq, Qb, IMGN, HIDW);
    GEMM_TC(OFF_HS, OFF_WK, bk, Kb, IMGN, HIDW);
    GEMM_TC(OFF_HS, OFF_WV, bv, VFb + (size_t)TXTN * HIDW, IMGN, HIDW);
    GEMM_TC(OFF_ENC, OFF_WQA, bqa, EQb, TXTN, HIDW);
    GEMM_TC(OFF_ENC, OFF_WKA, bka, EKb, TXTN, HIDW);
    GEMM_TC(OFF_ENC, OFF_WVA, bva, VFb, TXTN, HIDW);
    GEMM_TC(OFF_IP, OFF_WKIP, bkip, IPKb, 128, 1152);
    GEMM_TC(OFF_IP, OFF_WVIP, bvip, IPVb, 128, 1152);

    // --- RMS norms ---
    rms_kernel<<<dim3(IMGN, NHW), 128>>>(Qb, nipq, IPQb);
    rms_kernel<<<dim3(128, NHW), 128>>>(IPKb, nipk, IPKb);
    rms_kernel<<<dim3(IMGN, NHW), 128>>>(Qb, nqw, QFb + (size_t)TXTN * HIDW);
    rms_kernel<<<dim3(IMGN, NHW), 128>>>(Kb, nkw, KFb + (size_t)TXTN * HIDW);
    rms_kernel<<<dim3(TXTN, NHW), 128>>>(EQb, naqw, QFb);
    rms_kernel<<<dim3(TXTN, NHW), 128>>>(EKb, nakw, KFb);

    // --- RoPE ---
    rope_kernel<<<dim3(S_ALL, NHW), 128>>>(QFb, cosT, sinT);
    rope_kernel<<<dim3(S_ALL, NHW), 128>>>(KFb, cosT, sinT);

    // --- split attention operands to bf16 hi/lo ---
    {
        struct SplitJob2 { const float* src; size_t off; size_t n; };
        const SplitJob2 aj[6] = {
            {QFb,  OFF_QF,  4718592ull},
            {KFb,  OFF_KF,  4718592ull},
            {VFb,  OFF_VF,  4718592ull},
            {IPQb, OFF_IPQ, 3145728ull},
            {IPKb, OFF_IPK, 393216ull},
            {IPVb, OFF_IPV, 393216ull},
        };
        for (int j = 0; j < 6; j++) {
            int n4 = (int)(aj[j].n / 4);
            split_kernel<<<(n4 + 255) / 256, 256>>>(
                (const float4*)aj[j].src,
                (__nv_bfloat162*)(bh + aj[j].off),
                (__nv_bfloat162*)(bl + aj[j].off), n4);
        }
    }

    // --- flash attention (main + IP) ---
    flash_kernel<<<dim3(S_ALL / 128, NHW), blk, smem_fa>>>(
        bh + OFF_QF, bl + OFF_QF, bh + OFF_KF, bl + OFF_KF,
        bh + OFF_VF, bl + OFF_VF, ATb, S_ALL);
    flash_kernel<<<dim3(IMGN / 128, NHW), blk, smem_fa>>>(
        bh + OFF_IPQ, bl + OFF_IPQ, bh + OFF_IPK, bl + OFF_IPK,
        bh + OFF_IPV, bl + OFF_IPV, IPOb, 128);

    // --- mask add on img part ---
    maskadd_kernel<<<IMGN, blk>>>(ATb + (size_t)TXTN * HIDW, IPOb);

    // --- split attention outputs, then output projections ---
    {
        int n4 = (int)(3145728ull / 4);
        split_kernel<<<(n4 + 255) / 256, 256>>>(
            (const float4*)(ATb + (size_t)TXTN * HIDW),
            (__nv_bfloat162*)(bh + OFF_ATI), (__nv_bfloat162*)(bl + OFF_ATI), n4);
        n4 = (int)(1572864ull / 4);
        split_kernel<<<(n4 + 255) / 256, 256>>>(
            (const float4*)ATb,
            (__nv_bfloat162*)(bh + OFF_ATE), (__nv_bfloat162*)(bl + OFF_ATE), n4);
    }
    GEMM_TC(OFF_ATI, OFF_WOUT, bout, out_img, IMGN, HIDW);
    GEMM_TC(OFF_ATE, OFF_WAOUT, baout, out_enc, TXTN, HIDW);
#undef GEMM_TC
}

// round 8
// speedup vs baseline: 11.1391x; 1.6506x over previous
#include <cuda_runtime.h>
#include <cuda_bf16.h>

#define HIDW 3072
#define DHW  128
#define NHW  24
#define S_ALL 1536
#define TXTN 512
#define IMGN 1024

// fp32 scratch (intermediates)
__device__ float g_buf[11520ull * 3072ull];

#define O_Q     0
#define O_K     1024
#define O_EQ    2048
#define O_EK    2560
#define O_IPK   3072
#define O_ATTN  8960
#define O_IPOUT 10496

// bf16 hi/lo arenas
#define BF_TOT 110250000ull
__device__ __nv_bfloat16 g_bh[BF_TOT];
__device__ __nv_bfloat16 g_bl[BF_TOT];

#define OFF_WQ    0ull
#define OFF_WK    9437184ull
#define OFF_WV    18874368ull
#define OFF_WQA   28311552ull
#define OFF_WKA   37748736ull
#define OFF_WVA   47185920ull
#define OFF_WOUT  56623104ull
#define OFF_WAOUT 66060288ull
#define OFF_WKIP  75497472ull
#define OFF_WVIP  79036416ull
#define OFF_HS    82575360ull
#define OFF_ENC   85721088ull
#define OFF_IP    87293952ull
#define OFF_ATI   87441408ull
#define OFF_ATE   90587136ull
#define OFF_QF    92160000ull
#define OFF_KF    96878592ull
#define OFF_VF    101597184ull
#define OFF_IPQ   106315776ull
#define OFF_IPK   109461504ull
#define OFF_IPV   109854720ull

// ---------------------------------------------------------------------------
// PTX helpers
// ---------------------------------------------------------------------------
__device__ __forceinline__ unsigned smem_u32(const void* p) {
    return (unsigned)__cvta_generic_to_shared(p);
}
__device__ __forceinline__ void cp_async16(unsigned s, const void* g) {
    asm volatile("cp.async.cg.shared.global [%0], [%1], 16;" :: "r"(s), "l"(g));
}
#define CP_COMMIT() asm volatile("cp.async.commit_group;" ::: "memory")

#define LDSM_X4(r, addr) \
    asm volatile("ldmatrix.sync.aligned.m8n8.x4.shared.b16 {%0,%1,%2,%3}, [%4];" \
                 : "=r"((r)[0]), "=r"((r)[1]), "=r"((r)[2]), "=r"((r)[3]) \
                 : "r"(addr))
#define LDSM_X4T(r, addr) \
    asm volatile("ldmatrix.sync.aligned.m8n8.x4.trans.shared.b16 {%0,%1,%2,%3}, [%4];" \
                 : "=r"((r)[0]), "=r"((r)[1]), "=r"((r)[2]), "=r"((r)[3]) \
                 : "r"(addr))

__device__ __forceinline__ void mma16816(float* c, const unsigned* a,
                                         unsigned b0, unsigned b1) {
    asm volatile(
        "mma.sync.aligned.m16n8k16.row.col.f32.bf16.bf16.f32 "
        "{%0,%1,%2,%3}, {%4,%5,%6,%7}, {%8,%9}, {%0,%1,%2,%3};"
        : "+f"(c[0]), "+f"(c[1]), "+f"(c[2]), "+f"(c[3])
        : "r"(a[0]), "r"(a[1]), "r"(a[2]), "r"(a[3]), "r"(b0), "r"(b1));
}

__device__ __forceinline__ float fex2(float x) {
    float y;
    asm("ex2.approx.f32 %0, %1;" : "=f"(y) : "f"(x));
    return y;
}
__device__ __forceinline__ unsigned pack_bf2(float lo, float hi) {
    unsigned r;
    asm("cvt.rn.bf16x2.f32 %0, %1, %2;" : "=r"(r) : "f"(hi), "f"(lo));
    return r;
}

__device__ __forceinline__ unsigned sw64(int row, int cb) {
    return (unsigned)(row * 64 + (cb ^ (((row >> 1) & 3) << 4)));
}
__device__ __forceinline__ unsigned sw256(int row, int cb) {
    return (unsigned)(row * 256 + (cb ^ ((row & 7) << 4)));
}

// ---------------------------------------------------------------------------
// Multi-job split: fp32 -> bf16 hi + lo. One launch for all inputs.
// ---------------------------------------------------------------------------
struct SJob { const float4* src; __nv_bfloat162* hi; __nv_bfloat162* lo; int blk0; };
struct SJobs { SJob j[14]; int njobs; };

__global__ __launch_bounds__(256) void split_multi_kernel(SJobs jobs)
{
    int b = blockIdx.x;
    int ji = 0;
#pragma unroll 1
    while (ji + 1 < jobs.njobs && b >= jobs.j[ji + 1].blk0) ji++;
    const SJob J = jobs.j[ji];
    int i = (b - J.blk0) * 256 + threadIdx.x;
    float4 v = J.src[i];
    __nv_bfloat16 h0 = __float2bfloat16(v.x);
    __nv_bfloat16 h1 = __float2bfloat16(v.y);
    __nv_bfloat16 h2 = __float2bfloat16(v.z);
    __nv_bfloat16 h3 = __float2bfloat16(v.w);
    __nv_bfloat16 l0 = __float2bfloat16(v.x - __bfloat162float(h0));
    __nv_bfloat16 l1 = __float2bfloat16(v.y - __bfloat162float(h1));
    __nv_bfloat16 l2 = __float2bfloat16(v.z - __bfloat162float(h2));
    __nv_bfloat16 l3 = __float2bfloat16(v.w - __bfloat162float(h3));
    J.hi[2 * i]     = __halves2bfloat162(h0, h1);
    J.hi[2 * i + 1] = __halves2bfloat162(h2, h3);
    J.lo[2 * i]     = __halves2bfloat162(l0, l1);
    J.lo[2 * i + 1] = __halves2bfloat162(l2, l3);
}

// ---------------------------------------------------------------------------
// Multi-job mma.sync GEMM: C[M,3072] = A[M,K] @ B[3072,K]^T + bias (bf16x3).
// CTA 128x128, 8 warps, K chunk 32, 3-stage cp.async.
// mode 0: write fp32 C. mode 1: write bf16 hi/lo (split fused in epilogue).
// ---------------------------------------------------------------------------
#define GSTAGE 32768
#define GNSTG  3

struct GJob {
    const __nv_bfloat16 *Ah, *Al, *Bh, *Bl;
    const float* bias;
    float* C;
    __nv_bfloat16 *Oh, *Ol;
    int K, blk0, mode, pad;
};
struct GJobs { GJob j[8]; int njobs; };

__device__ __forceinline__ void gemm_load_stage(
    unsigned sbase, const __nv_bfloat16* a_h, const __nv_bfloat16* a_l,
    const __nv_bfloat16* b_h, const __nv_bfloat16* b_l, int K, int k0, int tid)
{
    const __nv_bfloat16* srcs[4] = {a_h, a_l, b_h, b_l};
#pragma unroll
    for (int j = 0; j < 4; j++) {
        const __nv_bfloat16* g = srcs[j] + k0;
#pragma unroll
        for (int i = 0; i < 2; i++) {
            int slot = i * 256 + tid;
            int row = slot >> 2;
            int cb = (slot & 3) * 16;
            cp_async16(sbase + j * 8192 + sw64(row, cb),
                       (const char*)g + (size_t)row * K * 2 + cb);
        }
    }
    CP_COMMIT();
}

__global__ __launch_bounds__(256, 2) void gemm_multi_kernel(GJobs jobs)
{
    extern __shared__ char gsm[];
    const unsigned sm0 = smem_u32(gsm);
    const int tid = threadIdx.x;
    const int w = tid >> 5, lane = tid & 31;
    const int wm = w & 1;
    const int wn = w >> 1;

    int b = blockIdx.x;
    int ji = 0;
#pragma unroll 1
    while (ji + 1 < jobs.njobs && b >= jobs.j[ji + 1].blk0) ji++;
    const GJob J = jobs.j[ji];
    const int rem = b - J.blk0;
    const int bn = (rem % 24) * 128;
    const int bm = (rem / 24) * 128;
    const int K = J.K;

    const __nv_bfloat16* a_h = J.Ah + (size_t)bm * K;
    const __nv_bfloat16* a_l = J.Al + (size_t)bm * K;
    const __nv_bfloat16* b_h = J.Bh + (size_t)bn * K;
    const __nv_bfloat16* b_l = J.Bl + (size_t)bn * K;

    const int nchunks = K >> 5;

    float acc[4][4][4];
#pragma unroll
    for (int i = 0; i < 4; i++)
#pragma unroll
        for (int j = 0; j < 4; j++)
#pragma unroll
            for (int q = 0; q < 4; q++) acc[i][j][q] = 0.f;

    gemm_load_stage(sm0, a_h, a_l, b_h, b_l, K, 0, tid);
    gemm_load_stage(sm0 + GSTAGE, a_h, a_l, b_h, b_l, K, 32, tid);

    for (int c = 0; c < nchunks; c++) {
        if (c + 2 < nchunks) {
            gemm_load_stage(sm0 + ((c + 2) % GNSTG) * GSTAGE,
                            a_h, a_l, b_h, b_l, K, (c + 2) << 5, tid);
            asm volatile("cp.async.wait_group 2;" ::: "memory");
        } else if (c + 1 < nchunks) {
            asm volatile("cp.async.wait_group 1;" ::: "memory");
        } else {
            asm volatile("cp.async.wait_group 0;" ::: "memory");
        }
        __syncthreads();

        const unsigned sbase = sm0 + (c % GNSTG) * GSTAGE;
        const unsigned aoff[3] = {0u, 0u, 8192u};
        const unsigned boff[3] = {16384u, 24576u, 16384u};
#pragma unroll
        for (int p = 0; p < 3; p++) {
            const unsigned sA = sbase + aoff[p];
            const unsigned sB = sbase + boff[p];
#pragma unroll
            for (int ks = 0; ks < 2; ks++) {
                const int kb = ks * 32;
                unsigned bf[2][4];
#pragma unroll
                for (int bt = 0; bt < 2; bt++) {
                    int row = wn * 32 + bt * 16 + (lane & 7) + ((lane >> 4) << 3);
                    int cb = kb + (((lane >> 3) & 1) << 4);
                    LDSM_X4(bf[bt], sB + sw64(row, cb));
                }
#pragma unroll
                for (int mt = 0; mt < 4; mt++) {
                    unsigned af[4];
                    {
                        int row = wm * 64 + mt * 16 + (lane & 15);
                        int cb = kb + ((lane >> 4) << 4);
                        LDSM_X4(af, sA + sw64(row, cb));
                    }
#pragma unroll
                    for (int nt = 0; nt < 4; nt++)
                        mma16816(acc[mt][nt], af,
                                 bf[nt >> 1][(nt & 1) * 2],
                                 bf[nt >> 1][(nt & 1) * 2 + 1]);
                }
            }
        }
        __syncthreads();
    }

    const int gq = lane >> 2, tig = lane & 3;
    if (J.mode == 0) {
#pragma unroll
        for (int mt = 0; mt < 4; mt++) {
#pragma unroll
            for (int nt = 0; nt < 4; nt++) {
                int row0 = bm + wm * 64 + mt * 16 + gq;
                int col = bn + wn * 32 + nt * 8 + tig * 2;
                float b0 = J.bias[col], b1 = J.bias[col + 1];
                *(float2*)(J.C + (size_t)row0 * HIDW + col) =
                    make_float2(acc[mt][nt][0] + b0, acc[mt][nt][1] + b1);
                *(float2*)(J.C + (size_t)(row0 + 8) * HIDW + col) =
                    make_float2(acc[mt][nt][2] + b0, acc[mt][nt][3] + b1);
            }
        }
    } else {
#pragma unroll
        for (int mt = 0; mt < 4; mt++) {
#pragma unroll
            for (int nt = 0; nt < 4; nt++) {
                int row0 = bm + wm * 64 + mt * 16 + gq;
                int col = bn + wn * 32 + nt * 8 + tig * 2;
                float b0 = J.bias[col], b1 = J.bias[col + 1];
                float v00 = acc[mt][nt][0] + b0, v01 = acc[mt][nt][1] + b1;
                float v10 = acc[mt][nt][2] + b0, v11 = acc[mt][nt][3] + b1;
                __nv_bfloat16 h00 = __float2bfloat16(v00);
                __nv_bfloat16 h01 = __float2bfloat16(v01);
                __nv_bfloat16 h10 = __float2bfloat16(v10);
                __nv_bfloat16 h11 = __float2bfloat16(v11);
                size_t o0 = (size_t)row0 * HIDW + col;
                size_t o1 = (size_t)(row0 + 8) * HIDW + col;
                *(__nv_bfloat162*)(J.Oh + o0) = __halves2bfloat162(h00, h01);
                *(__nv_bfloat162*)(J.Oh + o1) = __halves2bfloat162(h10, h11);
                *(__nv_bfloat162*)(J.Ol + o0) = __halves2bfloat162(
                    __float2bfloat16(v00 - __bfloat162float(h00)),
                    __float2bfloat16(v01 - __bfloat162float(h01)));
                *(__nv_bfloat162*)(J.Ol + o1) = __halves2bfloat162(
                    __float2bfloat16(v10 - __bfloat162float(h10)),
                    __float2bfloat16(v11 - __bfloat162float(h11)));
            }
        }
    }
}

// ---------------------------------------------------------------------------
// Flash attention on mma.sync with bf16 hi/lo 3-pass (unchanged from R7).
// ---------------------------------------------------------------------------
#define SCL2E 0.12751743f

__device__ __forceinline__ void fa_load_stage(
    unsigned sb, const char* kh, const char* kl, const char* vh, const char* vl,
    int kv0, size_t hb, int tid)
{
    const char* srcs[4] = {kh, kl, vh, vl};
#pragma unroll
    for (int j = 0; j < 4; j++) {
#pragma unroll
        for (int i = 0; i < 4; i++) {
            int slot = i * 256 + tid;
            int row = slot >> 4, cb = (slot & 15) * 16;
            cp_async16(sb + j * 16384 + sw256(row, cb),
                       srcs[j] + (size_t)(kv0 + row) * 6144 + hb + cb);
        }
    }
    CP_COMMIT();
}

__global__ __launch_bounds__(256, 1) void flash_kernel(
    const __nv_bfloat16* __restrict__ Qh, const __nv_bfloat16* __restrict__ Ql,
    const __nv_bfloat16* __restrict__ Kh, const __nv_bfloat16* __restrict__ Kl,
    const __nv_bfloat16* __restrict__ Vh, const __nv_bfloat16* __restrict__ Vl,
    float* __restrict__ O, int nkv)
{
    extern __shared__ char fsm[];
    const unsigned sQh = smem_u32(fsm);
    const unsigned sQl = sQh + 32768;
    const unsigned sStg = sQh + 65536;
    const int tid = threadIdx.x;
    const int w = tid >> 5, lane = tid & 31;
    const int gp = lane >> 2, tig = lane & 3;
    const int h = blockIdx.y;
    const int q0 = blockIdx.x * 128;
    const int m0 = w * 16;
    const size_t hb = (size_t)h * 256;

    {
        const char* gq[2] = {(const char*)Qh, (const char*)Ql};
        const unsigned sq[2] = {sQh, sQl};
#pragma unroll
        for (int t2 = 0; t2 < 2; t2++)
#pragma unroll
            for (int i = 0; i < 8; i++) {
                int slot = i * 256 + tid;
                int row = slot >> 4, cb = (slot & 15) * 16;
                cp_async16(sq[t2] + sw256(row, cb),
                           gq[t2] + (size_t)(q0 + row) * 6144 + hb + cb);
            }
        CP_COMMIT();
    }

    const int ntile = nkv >> 6;
    fa_load_stage(sStg, (const char*)Kh, (const char*)Kl,
                  (const char*)Vh, (const char*)Vl, 0, hb, tid);

    float o[16][4];
#pragma unroll
    for (int i = 0; i < 16; i++)
#pragma unroll
        for (int j = 0; j < 4; j++) o[i][j] = 0.f;
    float m_0 = -1e30f, m_1 = -1e30f;
    float l_0 = 0.f, l_1 = 0.f;

    for (int t = 0; t < ntile; t++) {
        if (t + 1 < ntile) {
            fa_load_stage(sStg + ((t + 1) & 1) * 65536, (const char*)Kh,
                          (const char*)Kl, (const char*)Vh, (const char*)Vl,
                          (t + 1) * 64, hb, tid);
            asm volatile("cp.async.wait_group 1;" ::: "memory");
        } else {
            asm volatile("cp.async.wait_group 0;" ::: "memory");
        }
        __syncthreads();

        const unsigned sb = sStg + (t & 1) * 65536;
        const unsigned sK_h = sb, sK_l = sb + 16384;
        const unsigned sV_h = sb + 32768, sV_l = sb + 49152;

        float s[8][4];
#pragma unroll
        for (int i = 0; i < 8; i++)
#pragma unroll
            for (int j = 0; j < 4; j++) s[i][j] = 0.f;

#pragma unroll
        for (int kc = 0; kc < 8; kc++) {
            const int arow = m0 + (lane & 15);
            const int acb = kc * 32 + ((lane >> 4) << 4);
            unsigned afh[4], afl[4];
            LDSM_X4(afh, sQh + sw256(arow, acb));
            LDSM_X4(afl, sQl + sw256(arow, acb));
            const int brow = (lane & 7) + ((lane >> 4) << 3);
            const int bcb = kc * 32 + (((lane >> 3) & 1) << 4);
#pragma unroll
            for (int bt = 0; bt < 4; bt++) {
                unsigned bh_[4], bl_[4];
                LDSM_X4(bh_, sK_h + sw256(bt * 16 + brow, bcb));
                LDSM_X4(bl_, sK_l + sw256(bt * 16 + brow, bcb));
                mma16816(s[2 * bt], afh, bh_[0], bh_[1]);
                mma16816(s[2 * bt + 1], afh, bh_[2], bh_[3]);
                mma16816(s[2 * bt], afh, bl_[0], bl_[1]);
                mma16816(s[2 * bt + 1], afh, bl_[2], bl_[3]);
                mma16816(s[2 * bt], afl, bh_[0], bh_[1]);
                mma16816(s[2 * bt + 1], afl, bh_[2], bh_[3]);
            }
        }

        float mx0 = -1e30f, mx1 = -1e30f;
#pragma unroll
        for (int nt = 0; nt < 8; nt++) {
            mx0 = fmaxf(mx0, fmaxf(s[nt][0], s[nt][1]));
            mx1 = fmaxf(mx1, fmaxf(s[nt][2], s[nt][3]));
        }
        mx0 = fmaxf(mx0, __shfl_xor_sync(0xffffffffu, mx0, 1));
        mx0 = fmaxf(mx0, __shfl_xor_sync(0xffffffffu, mx0, 2));
        mx1 = fmaxf(mx1, __shfl_xor_sync(0xffffffffu, mx1, 1));
        mx1 = fmaxf(mx1, __shfl_xor_sync(0xffffffffu, mx1, 2));
        const float mn0 = fmaxf(m_0, mx0), mn1 = fmaxf(m_1, mx1);
        const float al0 = fex2((m_0 - mn0) * SCL2E);
        const float al1 = fex2((m_1 - mn1) * SCL2E);
        m_0 = mn0; m_1 = mn1;

        float sum0 = 0.f, sum1 = 0.f;
        unsigned aPh[4][4], aPl[4][4];
#pragma unroll
        for (int nt = 0; nt < 8; nt++) {
            float p0 = fex2((s[nt][0] - mn0) * SCL2E);
            float p1 = fex2((s[nt][1] - mn0) * SCL2E);
            float p2 = fex2((s[nt][2] - mn1) * SCL2E);
            float p3 = fex2((s[nt][3] - mn1) * SCL2E);
            sum0 += p0 + p1;
            sum1 += p2 + p3;
            float h0 = __bfloat162float(__float2bfloat16(p0));
            float h1 = __bfloat162float(__float2bfloat16(p1));
            float h2 = __bfloat162float(__float2bfloat16(p2));
            float h3 = __bfloat162float(__float2bfloat16(p3));
            const int kc = nt >> 1, hf = (nt & 1) * 2;
            aPh[kc][hf] = pack_bf2(p0, p1);
            aPh[kc][hf + 1] = pack_bf2(p2, p3);
            aPl[kc][hf] = pack_bf2(p0 - h0, p1 - h1);
            aPl[kc][hf + 1] = pack_bf2(p2 - h2, p3 - h3);
        }
        sum0 += __shfl_xor_sync(0xffffffffu, sum0, 1);
        sum0 += __shfl_xor_sync(0xffffffffu, sum0, 2);
        sum1 += __shfl_xor_sync(0xffffffffu, sum1, 1);
        sum1 += __shfl_xor_sync(0xffffffffu, sum1, 2);
        l_0 = l_0 * al0 + sum0;
        l_1 = l_1 * al1 + sum1;

#pragma unroll
        for (int i = 0; i < 16; i++) {
            o[i][0] *= al0; o[i][1] *= al0;
            o[i][2] *= al1; o[i][3] *= al1;
        }

        const int vrow0 = (lane & 7) + (((lane >> 3) & 1) << 3);
        const int vcbl = (lane >> 4) << 4;
#pragma unroll
        for (int kc = 0; kc < 4; kc++) {
            const int vr = kc * 16 + vrow0;
#pragma unroll
            for (int nb = 0; nb < 8; nb++) {
                unsigned vh_[4], vl_[4];
                const int vcb = nb * 32 + vcbl;
                LDSM_X4T(vh_, sV_h + sw256(vr, vcb));
                LDSM_X4T(vl_, sV_l + sw256(vr, vcb));
                mma16816(o[2 * nb], aPh[kc], vh_[0], vh_[1]);
                mma16816(o[2 * nb + 1], aPh[kc], vh_[2], vh_[3]);
                mma16816(o[2 * nb], aPh[kc], vl_[0], vl_[1]);
                mma16816(o[2 * nb + 1], aPh[kc], vl_[2], vl_[3]);
                mma16816(o[2 * nb], aPl[kc], vh_[0], vh_[1]);
                mma16816(o[2 * nb + 1], aPl[kc], vh_[2], vh_[3]);
            }
        }
        __syncthreads();
    }

    const float inv0 = 1.0f / l_0, inv1 = 1.0f / l_1;
    const int row0 = q0 + m0 + gp;
#pragma unroll
    for (int nt = 0; nt < 16; nt++) {
        const int col = h * 128 + nt * 8 + tig * 2;
        *(float2*)(O + (size_t)row0 * HIDW + col) =
            make_float2(o[nt][0] * inv0, o[nt][1] * inv0);
        *(float2*)(O + (size_t)(row0 + 8) * HIDW + col) =
            make_float2(o[nt][2] * inv1, o[nt][3] * inv1);
    }
}

// ---------------------------------------------------------------------------
// Fused rms + rope + bf16-split for Q, K, IPQ, IPK. One launch.
// grid.x: [0,1536) Q | [1536,3072) K | [3072,4096) IPQ | [4096,4224) IPK
// grid.y: head. block 128.
// ---------------------------------------------------------------------------
__global__ void fuse_qk_kernel(
    const float* __restrict__ Qb, const float* __restrict__ Kb,
    const float* __restrict__ EQb, const float* __restrict__ EKb,
    const float* __restrict__ IPKb,
    const float* __restrict__ nqw, const float* __restrict__ nkw,
    const float* __restrict__ naqw, const float* __restrict__ nakw,
    const float* __restrict__ nipq, const float* __restrict__ nipk,
    const float* __restrict__ cosT, const float* __restrict__ sinT,
    __nv_bfloat16* __restrict__ bh, __nv_bfloat16* __restrict__ bl)
{
    const int r = blockIdx.x;
    const int h = blockIdx.y;
    const int d = threadIdx.x;

    const float* src;
    const float* wv;
    size_t obase;
    int row_out;
    bool do_rope;

    if (r < 1536) {                     // Q (concat eq | qh)
        row_out = r; do_rope = true; obase = OFF_QF;
        if (r < 512) { src = EQb + (size_t)r * HIDW; wv = naqw; }
        else         { src = Qb + (size_t)(r - 512) * HIDW; wv = nqw; }
    } else if (r < 3072) {              // K (concat ek | kh)
        row_out = r - 1536; do_rope = true; obase = OFF_KF;
        if (row_out < 512) { src = EKb + (size_t)row_out * HIDW; wv = nakw; }
        else               { src = Kb + (size_t)(row_out - 512) * HIDW; wv = nkw; }
    } else if (r < 4096) {              // IPQ (rms of q, no rope)
        row_out = r - 3072; do_rope = false; obase = OFF_IPQ;
        src = Qb + (size_t)row_out * HIDW; wv = nipq;
    } else {                            // IPK
        row_out = r - 4096; do_rope = false; obase = OFF_IPK;
        src = IPKb + (size_t)row_out * HIDW; wv = nipk;
    }

    float x = src[h * DHW + d];
    float v = x * x;
#pragma unroll
    for (int off = 16; off > 0; off >>= 1)
        v += __shfl_xor_sync(0xffffffffu, v, off);
    __shared__ float ws[4];
    __shared__ float sx[128];
    const int lane = d & 31, wid = d >> 5;
    if (lane == 0) ws[wid] = v;
    __syncthreads();
    float total = ws[0] + ws[1] + ws[2] + ws[3];
    float y = x * rsqrtf(total * (1.0f / 128.0f) + 1e-6f) * wv[d];

    if (do_rope) {
        sx[d] = y;
        __syncthreads();
        float c = cosT[row_out * DHW + d];
        float s = sinT[row_out * DHW + d];
        float yr = (d & 1) ? sx[d - 1] : -sx[d + 1];
        y = y * c + yr * s;
    }

    __nv_bfloat16 hi = __float2bfloat16(y);
    size_t o = obase + (size_t)row_out * HIDW + h * DHW + d;
    bh[o] = hi;
    bl[o] = __float2bfloat16(y - __bfloat162float(hi));
}

// ---------------------------------------------------------------------------
// Fused maskadd + AT splits. grid 1536, block 256.
// rows [0,512): AT enc -> ATE hi/lo ; rows [512,1536): AT img (+IPO) -> ATI.
// ---------------------------------------------------------------------------
__global__ __launch_bounds__(256) void fuse_at_kernel(
    const float* __restrict__ AT, const float* __restrict__ IPO,
    __nv_bfloat16* __restrict__ bh, __nv_bfloat16* __restrict__ bl)
{
    const int r = blockIdx.x;
    const float* arow = AT + (size_t)r * HIDW;
    size_t obase;
    const float* adder = nullptr;
    if (r < 512) {
        obase = OFF_ATE + (size_t)r * HIDW;
    } else {
        int i = r - 512;
        obase = OFF_ATI + (size_t)i * HIDW;
        int y = i >> 5, x = i & 31;
        if (y >= 8 && y < 24 && x >= 8 && x < 24)
            adder = IPO + (size_t)i * HIDW;
    }
    for (int c = threadIdx.x; c < HIDW; c += 256) {
        float v = arow[c];
        if (adder) v += adder[c];
        __nv_bfloat16 hi = __float2bfloat16(v);
        bh[obase + c] = hi;
        bl[obase + c] = __float2bfloat16(v - __bfloat162float(hi));
    }
}

// ---------------------------------------------------------------------------
extern "C" void kernel_launch(void* const* d_in, const int* in_sizes, int n_in,
                              void* d_out, int out_size)
{
    const float* hs    = (const float*)d_in[0];
    const float* enc   = (const float*)d_in[1];
    const float* ip    = (const float*)d_in[2];
    const float* cosT  = (const float*)d_in[3];
    const float* sinT  = (const float*)d_in[4];
    const float* bq    = (const float*)d_in[6];
    const float* bk    = (const float*)d_in[8];
    const float* bv    = (const float*)d_in[10];
    const float* nqw   = (const float*)d_in[11];
    const float* nkw   = (const float*)d_in[12];
    const float* bqa   = (const float*)d_in[14];
    const float* bka   = (const float*)d_in[16];
    const float* bva   = (const float*)d_in[18];
    const float* naqw  = (const float*)d_in[19];
    const float* nakw  = (const float*)d_in[20];
    const float* bout  = (const float*)d_in[22];
    const float* baout = (const float*)d_in[24];
    const float* bkip  = (const float*)d_in[26];
    const float* bvip  = (const float*)d_in[28];
    const float* nipq  = (const float*)d_in[29];
    const float* nipk  = (const float*)d_in[30];

    float* buf = nullptr;
    cudaGetSymbolAddress((void**)&buf, g_buf);
    __nv_bfloat16* bh = nullptr;
    __nv_bfloat16* bl = nullptr;
    cudaGetSymbolAddress((void**)&bh, g_bh);
    cudaGetSymbolAddress((void**)&bl, g_bl);

    float* Qb   = buf + (size_t)O_Q * HIDW;
    float* Kb   = buf + (size_t)O_K * HIDW;
    float* EQb  = buf + (size_t)O_EQ * HIDW;
    float* EKb  = buf + (size_t)O_EK * HIDW;
    float* IPKb = buf + (size_t)O_IPK * HIDW;
    float* ATb  = buf + (size_t)O_ATTN * HIDW;
    float* IPOb = buf + (size_t)O_IPOUT * HIDW;

    float* out_img = (float*)d_out;
    float* out_enc = (float*)d_out + (size_t)IMGN * HIDW;

    const int smem_gemm = GNSTG * GSTAGE;       // 98304
    const int smem_fa   = 196608;
    cudaFuncSetAttribute(gemm_multi_kernel, cudaFuncAttributeMaxDynamicSharedMemorySize,
                         smem_gemm);
    cudaFuncSetAttribute(flash_kernel, cudaFuncAttributeMaxDynamicSharedMemorySize,
                         smem_fa);

    // ---- 1) all input splits in one launch ----
    {
        struct HostSJob { const float* src; size_t off; size_t n; };
        const HostSJob hj[13] = {
            {(const float*)d_in[5],  OFF_WQ,    9437184ull},
            {(const float*)d_in[7],  OFF_WK,    9437184ull},
            {(const float*)d_in[9],  OFF_WV,    9437184ull},
            {(const float*)d_in[13], OFF_WQA,   9437184ull},
            {(const float*)d_in[15], OFF_WKA,   9437184ull},
            {(const float*)d_in[17], OFF_WVA,   9437184ull},
            {(const float*)d_in[21], OFF_WOUT,  9437184ull},
            {(const float*)d_in[23], OFF_WAOUT, 9437184ull},
            {(const float*)d_in[25], OFF_WKIP,  3538944ull},
            {(const float*)d_in[27], OFF_WVIP,  3538944ull},
            {hs,  OFF_HS,  3145728ull},
            {enc, OFF_ENC, 1572864ull},
            {ip,  OFF_IP,  147456ull},
        };
        SJobs js;
        js.njobs = 13;
        int blk = 0;
        for (int j = 0; j < 13; j++) {
            js.j[j].src = (const float4*)hj[j].src;
            js.j[j].hi = (__nv_bfloat162*)(bh + hj[j].off);
            js.j[j].lo = (__nv_bfloat162*)(bl + hj[j].off);
            js.j[j].blk0 = blk;
            blk += (int)(hj[j].n / 1024);
        }
        split_multi_kernel<<<blk, 256>>>(js);
    }

    // ---- 2) all 8 projections in one GEMM launch ----
    {
        GJobs gj;
        gj.njobs = 8;
        auto setj = [&](int i, size_t offA, size_t offB, const float* bias,
                        float* C, __nv_bfloat16* Oh, __nv_bfloat16* Ol,
                        int M, int K, int& blk) {
            gj.j[i].Ah = bh + offA; gj.j[i].Al = bl + offA;
            gj.j[i].Bh = bh + offB; gj.j[i].Bl = bl + offB;
            gj.j[i].bias = bias; gj.j[i].C = C;
            gj.j[i].Oh = Oh; gj.j[i].Ol = Ol;
            gj.j[i].K = K; gj.j[i].blk0 = blk;
            gj.j[i].mode = (Oh != nullptr) ? 1 : 0;
            blk += (M / 128) * 24;
        };
        int blk = 0;
        setj(0, OFF_HS, OFF_WQ, bq, Qb, nullptr, nullptr, IMGN, HIDW, blk);
        setj(1, OFF_HS, OFF_WK, bk, Kb, nullptr, nullptr, IMGN, HIDW, blk);
        setj(2, OFF_HS, OFF_WV, bv, nullptr,
             bh + OFF_VF + (size_t)TXTN * HIDW, bl + OFF_VF + (size_t)TXTN * HIDW,
             IMGN, HIDW, blk);
        setj(3, OFF_ENC, OFF_WQA, bqa, EQb, nullptr, nullptr, TXTN, HIDW, blk);
        setj(4, OFF_ENC, OFF_WKA, bka, EKb, nullptr, nullptr, TXTN, HIDW, blk);
        setj(5, OFF_ENC, OFF_WVA, bva, nullptr,
             bh + OFF_VF, bl + OFF_VF, TXTN, HIDW, blk);
        setj(6, OFF_IP, OFF_WKIP, bkip, IPKb, nullptr, nullptr, 128, 1152, blk);
        setj(7, OFF_IP, OFF_WVIP, bvip, nullptr,
             bh + OFF_IPV, bl + OFF_IPV, 128, 1152, blk);
        gemm_multi_kernel<<<blk, 256, smem_gemm>>>(gj);
    }

    // ---- 3) fused rms + rope + split ----
    fuse_qk_kernel<<<dim3(4224, NHW), 128>>>(
        Qb, Kb, EQb, EKb, IPKb, nqw, nkw, naqw, nakw, nipq, nipk,
        cosT, sinT, bh, bl);

    // ---- 4) flash attention ----
    flash_kernel<<<dim3(S_ALL / 128, NHW), 256, smem_fa>>>(
        bh + OFF_QF, bl + OFF_QF, bh + OFF_KF, bl + OFF_KF,
        bh + OFF_VF, bl + OFF_VF, ATb, S_ALL);
    flash_kernel<<<dim3(IMGN / 128, NHW), 256, smem_fa>>>(
        bh + OFF_IPQ, bl + OFF_IPQ, bh + OFF_IPK, bl + OFF_IPK,
        bh + OFF_IPV, bl + OFF_IPV, IPOb, 128);

    // ---- 5) fused maskadd + AT splits ----
    fuse_at_kernel<<<S_ALL, 256>>>(ATb, IPOb, bh, bl);

    // ---- 6) output projections in one GEMM launch ----
    {
        GJobs gj;
        gj.njobs = 2;
        int blk = 0;
        gj.j[0].Ah = bh + OFF_ATI; gj.j[0].Al = bl + OFF_ATI;
        gj.j[0].Bh = bh + OFF_WOUT; gj.j[0].Bl = bl + OFF_WOUT;
        gj.j[0].bias = bout; gj.j[0].C = out_img;
        gj.j[0].Oh = nullptr; gj.j[0].Ol = nullptr;
        gj.j[0].K = HIDW; gj.j[0].blk0 = blk; gj.j[0].mode = 0;
        blk += (IMGN / 128) * 24;
        gj.j[1].Ah = bh + OFF_ATE; gj.j[1].Al = bl + OFF_ATE;
        gj.j[1].Bh = bh + OFF_WAOUT; gj.j[1].Bl = bl + OFF_WAOUT;
        gj.j[1].bias = baout; gj.j[1].C = out_enc;
        gj.j[1].Oh = nullptr; gj.j[1].Ol = nullptr;
        gj.j[1].K = HIDW; gj.j[1].blk0 = blk; gj.j[1].mode = 0;
        blk += (TXTN / 128) * 24;
        gemm_multi_kernel<<<blk, 256, smem_gemm>>>(gj);
    }
}

// round 9
// speedup vs baseline: 12.3231x; 1.1063x over previous
#include <cuda_runtime.h>
#include <cuda_bf16.h>

#define HIDW 3072
#define DHW  128
#define NHW  24
#define S_ALL 1536
#define TXTN 512
#define IMGN 1024

// fp32 scratch (intermediates)
__device__ float g_buf[11520ull * 3072ull];

#define O_Q     0
#define O_K     1024
#define O_EQ    2048
#define O_EK    2560
#define O_IPK   3072
#define O_ATTN  8960
#define O_IPOUT 10496

// bf16 hi/lo arenas (flash operands only now)
#define BF_TOT 110250000ull
__device__ __nv_bfloat16 g_bh[BF_TOT];
__device__ __nv_bfloat16 g_bl[BF_TOT];

#define OFF_QF    92160000ull
#define OFF_KF    96878592ull
#define OFF_VF    101597184ull
#define OFF_IPQ   106315776ull
#define OFF_IPK   109461504ull
#define OFF_IPV   109854720ull

// ---------------------------------------------------------------------------
// PTX helpers
// ---------------------------------------------------------------------------
__device__ __forceinline__ unsigned smem_u32(const void* p) {
    return (unsigned)__cvta_generic_to_shared(p);
}
__device__ __forceinline__ void cp_async16(unsigned s, const void* g) {
    asm volatile("cp.async.cg.shared.global [%0], [%1], 16;" :: "r"(s), "l"(g));
}
#define CP_COMMIT() asm volatile("cp.async.commit_group;" ::: "memory")

#define LDSM_X4(r, addr) \
    asm volatile("ldmatrix.sync.aligned.m8n8.x4.shared.b16 {%0,%1,%2,%3}, [%4];" \
                 : "=r"((r)[0]), "=r"((r)[1]), "=r"((r)[2]), "=r"((r)[3]) \
                 : "r"(addr))
#define LDSM_X4T(r, addr) \
    asm volatile("ldmatrix.sync.aligned.m8n8.x4.trans.shared.b16 {%0,%1,%2,%3}, [%4];" \
                 : "=r"((r)[0]), "=r"((r)[1]), "=r"((r)[2]), "=r"((r)[3]) \
                 : "r"(addr))

__device__ __forceinline__ void mma16816(float* c, const unsigned* a,
                                         unsigned b0, unsigned b1) {
    asm volatile(
        "mma.sync.aligned.m16n8k16.row.col.f32.bf16.bf16.f32 "
        "{%0,%1,%2,%3}, {%4,%5,%6,%7}, {%8,%9}, {%0,%1,%2,%3};"
        : "+f"(c[0]), "+f"(c[1]), "+f"(c[2]), "+f"(c[3])
        : "r"(a[0]), "r"(a[1]), "r"(a[2]), "r"(a[3]), "r"(b0), "r"(b1));
}

__device__ __forceinline__ float fex2(float x) {
    float y;
    asm("ex2.approx.f32 %0, %1;" : "=f"(y) : "f"(x));
    return y;
}
// packs (first, second) -> bf16x2 in memory order first,second
__device__ __forceinline__ unsigned pack_bf2(float a, float b) {
    unsigned r;
    asm("cvt.rn.bf16x2.f32 %0, %1, %2;" : "=r"(r) : "f"(b), "f"(a));
    return r;
}

__device__ __forceinline__ unsigned sw64(int row, int cb) {
    return (unsigned)(row * 64 + (cb ^ (((row >> 1) & 3) << 4)));
}
__device__ __forceinline__ unsigned sw256(int row, int cb) {
    return (unsigned)(row * 256 + (cb ^ ((row & 7) << 4)));
}

// ---------------------------------------------------------------------------
// Multi-job mma.sync GEMM consuming fp32 A/B directly.
// C[M,3072] = A[M,K] @ B[3072,K]^T + bias via in-kernel bf16 hi/lo split (3-pass).
// smem: 2 fp32 stages (32 KB each) + 1 bf16 hi/lo buffer (32 KB) = 96 KB.
// mode 0: fp32 C out. mode 1: bf16 hi/lo out.
// ---------------------------------------------------------------------------
struct GJob {
    const float *A, *B, *bias;
    float* C;
    __nv_bfloat16 *Oh, *Ol;
    int K, blk0, mode, pad;
};
struct GJobs { GJob j[8]; int njobs; };

__device__ __forceinline__ void gload_f32(
    unsigned stg, const float* A, const float* B, int K, int k0, int tid)
{
    const float* srcs[2] = {A + k0, B + k0};
#pragma unroll
    for (int m = 0; m < 2; m++) {
        const float* g = srcs[m];
#pragma unroll
        for (int i = 0; i < 4; i++) {
            int slot = i * 256 + tid;       // 0..1023
            int row = slot >> 3, c16 = slot & 7;
            unsigned off = row * 128 + ((c16 * 16) ^ ((row & 1) << 6));
            cp_async16(stg + m * 16384 + off,
                       (const char*)g + (size_t)row * K * 4 + c16 * 16);
        }
    }
    CP_COMMIT();
}

__device__ __forceinline__ void gconvert(unsigned stg, unsigned buf, int tid)
{
#pragma unroll
    for (int m = 0; m < 2; m++) {
        const unsigned sb = stg + m * 16384;
        const unsigned dh = buf + m * 16384;   // Ah at 0, Bh at 16384
        const unsigned dl = dh + 8192;         // Al at 8192, Bl at 24576
#pragma unroll
        for (int i = 0; i < 4; i++) {
            int slot = i * 256 + tid;          // 0..1023
            int row = slot >> 3, c16 = slot & 7;
            unsigned soff = sb + row * 128 + ((c16 * 16) ^ ((row & 1) << 6));
            float4 v;
            asm volatile("ld.shared.v4.f32 {%0,%1,%2,%3}, [%4];"
                         : "=f"(v.x), "=f"(v.y), "=f"(v.z), "=f"(v.w)
                         : "r"(soff));
            unsigned h01 = pack_bf2(v.x, v.y);
            unsigned h23 = pack_bf2(v.z, v.w);
            float hx = __bfloat162float(__float2bfloat16(v.x));
            float hy = __bfloat162float(__float2bfloat16(v.y));
            float hz = __bfloat162float(__float2bfloat16(v.z));
            float hw = __bfloat162float(__float2bfloat16(v.w));
            unsigned l01 = pack_bf2(v.x - hx, v.y - hy);
            unsigned l23 = pack_bf2(v.z - hz, v.w - hw);
            unsigned doff = row * 64 + ((c16 * 8) ^ (((row >> 1) & 3) << 4));
            asm volatile("st.shared.v2.b32 [%0], {%1,%2};"
                         :: "r"(dh + doff), "r"(h01), "r"(h23) : "memory");
            asm volatile("st.shared.v2.b32 [%0], {%1,%2};"
                         :: "r"(dl + doff), "r"(l01), "r"(l23) : "memory");
        }
    }
}

__global__ __launch_bounds__(256, 2) void gemm_multi_kernel(GJobs jobs)
{
    extern __shared__ char gsm[];
    const unsigned sm0 = smem_u32(gsm);
    const unsigned stg0 = sm0, stg1 = sm0 + 32768, bufb = sm0 + 65536;
    const int tid = threadIdx.x;
    const int w = tid >> 5, lane = tid & 31;
    const int wm = w & 1;
    const int wn = w >> 1;

    int b = blockIdx.x;
    int ji = 0;
#pragma unroll 1
    while (ji + 1 < jobs.njobs && b >= jobs.j[ji + 1].blk0) ji++;
    const GJob J = jobs.j[ji];
    const int rem = b - J.blk0;
    const int bn = (rem % 24) * 128;
    const int bm = (rem / 24) * 128;
    const int K = J.K;

    const float* a_f = J.A + (size_t)bm * K;
    const float* b_f = J.B + (size_t)bn * K;

    const int nchunks = K >> 5;

    float acc[4][4][4];
#pragma unroll
    for (int i = 0; i < 4; i++)
#pragma unroll
        for (int j = 0; j < 4; j++)
#pragma unroll
            for (int q = 0; q < 4; q++) acc[i][j][q] = 0.f;

    gload_f32(stg0, a_f, b_f, K, 0, tid);
    gload_f32(stg1, a_f, b_f, K, 32, tid);

    for (int c = 0; c < nchunks; c++) {
        if (c + 1 < nchunks)
            asm volatile("cp.async.wait_group 1;" ::: "memory");
        else
            asm volatile("cp.async.wait_group 0;" ::: "memory");
        __syncthreads();                       // prior mma done + stage visible
        gconvert((c & 1) ? stg1 : stg0, bufb, tid);
        __syncthreads();
        if (c + 2 < nchunks)
            gload_f32((c & 1) ? stg1 : stg0, a_f, b_f, K, (c + 2) << 5, tid);

        const unsigned aoff[3] = {0u, 0u, 8192u};          // Ah, Ah, Al
        const unsigned boff[3] = {16384u, 24576u, 16384u}; // Bh, Bl, Bh
#pragma unroll
        for (int p = 0; p < 3; p++) {
            const unsigned sA = bufb + aoff[p];
            const unsigned sB = bufb + boff[p];
#pragma unroll
            for (int ks = 0; ks < 2; ks++) {
                const int kb = ks * 32;
                unsigned bf[2][4];
#pragma unroll
                for (int bt = 0; bt < 2; bt++) {
                    int row = wn * 32 + bt * 16 + (lane & 7) + ((lane >> 4) << 3);
                    int cb = kb + (((lane >> 3) & 1) << 4);
                    LDSM_X4(bf[bt], sB + sw64(row, cb));
                }
#pragma unroll
                for (int mt = 0; mt < 4; mt++) {
                    unsigned af[4];
                    {
                        int row = wm * 64 + mt * 16 + (lane & 15);
                        int cb = kb + ((lane >> 4) << 4);
                        LDSM_X4(af, sA + sw64(row, cb));
                    }
#pragma unroll
                    for (int nt = 0; nt < 4; nt++)
                        mma16816(acc[mt][nt], af,
                                 bf[nt >> 1][(nt & 1) * 2],
                                 bf[nt >> 1][(nt & 1) * 2 + 1]);
                }
            }
        }
    }

    const int gq = lane >> 2, tig = lane & 3;
    if (J.mode == 0) {
#pragma unroll
        for (int mt = 0; mt < 4; mt++) {
#pragma unroll
            for (int nt = 0; nt < 4; nt++) {
                int row0 = bm + wm * 64 + mt * 16 + gq;
                int col = bn + wn * 32 + nt * 8 + tig * 2;
                float b0 = J.bias[col], b1 = J.bias[col + 1];
                *(float2*)(J.C + (size_t)row0 * HIDW + col) =
                    make_float2(acc[mt][nt][0] + b0, acc[mt][nt][1] + b1);
                *(float2*)(J.C + (size_t)(row0 + 8) * HIDW + col) =
                    make_float2(acc[mt][nt][2] + b0, acc[mt][nt][3] + b1);
            }
        }
    } else {
#pragma unroll
        for (int mt = 0; mt < 4; mt++) {
#pragma unroll
            for (int nt = 0; nt < 4; nt++) {
                int row0 = bm + wm * 64 + mt * 16 + gq;
                int col = bn + wn * 32 + nt * 8 + tig * 2;
                float b0 = J.bias[col], b1 = J.bias[col + 1];
                float v00 = acc[mt][nt][0] + b0, v01 = acc[mt][nt][1] + b1;
                float v10 = acc[mt][nt][2] + b0, v11 = acc[mt][nt][3] + b1;
                __nv_bfloat16 h00 = __float2bfloat16(v00);
                __nv_bfloat16 h01 = __float2bfloat16(v01);
                __nv_bfloat16 h10 = __float2bfloat16(v10);
                __nv_bfloat16 h11 = __float2bfloat16(v11);
                size_t o0 = (size_t)row0 * HIDW + col;
                size_t o1 = (size_t)(row0 + 8) * HIDW + col;
                *(__nv_bfloat162*)(J.Oh + o0) = __halves2bfloat162(h00, h01);
                *(__nv_bfloat162*)(J.Oh + o1) = __halves2bfloat162(h10, h11);
                *(__nv_bfloat162*)(J.Ol + o0) = __halves2bfloat162(
                    __float2bfloat16(v00 - __bfloat162float(h00)),
                    __float2bfloat16(v01 - __bfloat162float(h01)));
                *(__nv_bfloat162*)(J.Ol + o1) = __halves2bfloat162(
                    __float2bfloat16(v10 - __bfloat162float(h10)),
                    __float2bfloat16(v11 - __bfloat162float(h11)));
            }
        }
    }
}

// ---------------------------------------------------------------------------
// Flash attention on mma.sync with bf16 hi/lo 3-pass (unchanged).
// ---------------------------------------------------------------------------
#define SCL2E 0.12751743f

__device__ __forceinline__ void fa_load_stage(
    unsigned sb, const char* kh, const char* kl, const char* vh, const char* vl,
    int kv0, size_t hb, int tid)
{
    const char* srcs[4] = {kh, kl, vh, vl};
#pragma unroll
    for (int j = 0; j < 4; j++) {
#pragma unroll
        for (int i = 0; i < 4; i++) {
            int slot = i * 256 + tid;
            int row = slot >> 4, cb = (slot & 15) * 16;
            cp_async16(sb + j * 16384 + sw256(row, cb),
                       srcs[j] + (size_t)(kv0 + row) * 6144 + hb + cb);
        }
    }
    CP_COMMIT();
}

__global__ __launch_bounds__(256, 1) void flash_kernel(
    const __nv_bfloat16* __restrict__ Qh, const __nv_bfloat16* __restrict__ Ql,
    const __nv_bfloat16* __restrict__ Kh, const __nv_bfloat16* __restrict__ Kl,
    const __nv_bfloat16* __restrict__ Vh, const __nv_bfloat16* __restrict__ Vl,
    float* __restrict__ O, int nkv)
{
    extern __shared__ char fsm[];
    const unsigned sQh = smem_u32(fsm);
    const unsigned sQl = sQh + 32768;
    const unsigned sStg = sQh + 65536;
    const int tid = threadIdx.x;
    const int w = tid >> 5, lane = tid & 31;
    const int gp = lane >> 2, tig = lane & 3;
    const int h = blockIdx.y;
    const int q0 = blockIdx.x * 128;
    const int m0 = w * 16;
    const size_t hb = (size_t)h * 256;

    {
        const char* gq[2] = {(const char*)Qh, (const char*)Ql};
        const unsigned sq[2] = {sQh, sQl};
#pragma unroll
        for (int t2 = 0; t2 < 2; t2++)
#pragma unroll
            for (int i = 0; i < 8; i++) {
                int slot = i * 256 + tid;
                int row = slot >> 4, cb = (slot & 15) * 16;
                cp_async16(sq[t2] + sw256(row, cb),
                           gq[t2] + (size_t)(q0 + row) * 6144 + hb + cb);
            }
        CP_COMMIT();
    }

    const int ntile = nkv >> 6;
    fa_load_stage(sStg, (const char*)Kh, (const char*)Kl,
                  (const char*)Vh, (const char*)Vl, 0, hb, tid);

    float o[16][4];
#pragma unroll
    for (int i = 0; i < 16; i++)
#pragma unroll
        for (int j = 0; j < 4; j++) o[i][j] = 0.f;
    float m_0 = -1e30f, m_1 = -1e30f;
    float l_0 = 0.f, l_1 = 0.f;

    for (int t = 0; t < ntile; t++) {
        if (t + 1 < ntile) {
            fa_load_stage(sStg + ((t + 1) & 1) * 65536, (const char*)Kh,
                          (const char*)Kl, (const char*)Vh, (const char*)Vl,
                          (t + 1) * 64, hb, tid);
            asm volatile("cp.async.wait_group 1;" ::: "memory");
        } else {
            asm volatile("cp.async.wait_group 0;" ::: "memory");
        }
        __syncthreads();

        const unsigned sb = sStg + (t & 1) * 65536;
        const unsigned sK_h = sb, sK_l = sb + 16384;
        const unsigned sV_h = sb + 32768, sV_l = sb + 49152;

        float s[8][4];
#pragma unroll
        for (int i = 0; i < 8; i++)
#pragma unroll
            for (int j = 0; j < 4; j++) s[i][j] = 0.f;

#pragma unroll
        for (int kc = 0; kc < 8; kc++) {
            const int arow = m0 + (lane & 15);
            const int acb = kc * 32 + ((lane >> 4) << 4);
            unsigned afh[4], afl[4];
            LDSM_X4(afh, sQh + sw256(arow, acb));
            LDSM_X4(afl, sQl + sw256(arow, acb));
            const int brow = (lane & 7) + ((lane >> 4) << 3);
            const int bcb = kc * 32 + (((lane >> 3) & 1) << 4);
#pragma unroll
            for (int bt = 0; bt < 4; bt++) {
                unsigned bh_[4], bl_[4];
                LDSM_X4(bh_, sK_h + sw256(bt * 16 + brow, bcb));
                LDSM_X4(bl_, sK_l + sw256(bt * 16 + brow, bcb));
                mma16816(s[2 * bt], afh, bh_[0], bh_[1]);
                mma16816(s[2 * bt + 1], afh, bh_[2], bh_[3]);
                mma16816(s[2 * bt], afh, bl_[0], bl_[1]);
                mma16816(s[2 * bt + 1], afh, bl_[2], bl_[3]);
                mma16816(s[2 * bt], afl, bh_[0], bh_[1]);
                mma16816(s[2 * bt + 1], afl, bh_[2], bh_[3]);
            }
        }

        float mx0 = -1e30f, mx1 = -1e30f;
#pragma unroll
        for (int nt = 0; nt < 8; nt++) {
            mx0 = fmaxf(mx0, fmaxf(s[nt][0], s[nt][1]));
            mx1 = fmaxf(mx1, fmaxf(s[nt][2], s[nt][3]));
        }
        mx0 = fmaxf(mx0, __shfl_xor_sync(0xffffffffu, mx0, 1));
        mx0 = fmaxf(mx0, __shfl_xor_sync(0xffffffffu, mx0, 2));
        mx1 = fmaxf(mx1, __shfl_xor_sync(0xffffffffu, mx1, 1));
        mx1 = fmaxf(mx1, __shfl_xor_sync(0xffffffffu, mx1, 2));
        const float mn0 = fmaxf(m_0, mx0), mn1 = fmaxf(m_1, mx1);
        const float al0 = fex2((m_0 - mn0) * SCL2E);
        const float al1 = fex2((m_1 - mn1) * SCL2E);
        m_0 = mn0; m_1 = mn1;

        float sum0 = 0.f, sum1 = 0.f;
        unsigned aPh[4][4], aPl[4][4];
#pragma unroll
        for (int nt = 0; nt < 8; nt++) {
            float p0 = fex2((s[nt][0] - mn0) * SCL2E);
            float p1 = fex2((s[nt][1] - mn0) * SCL2E);
            float p2 = fex2((s[nt][2] - mn1) * SCL2E);
            float p3 = fex2((s[nt][3] - mn1) * SCL2E);
            sum0 += p0 + p1;
            sum1 += p2 + p3;
            float h0 = __bfloat162float(__float2bfloat16(p0));
            float h1 = __bfloat162float(__float2bfloat16(p1));
            float h2 = __bfloat162float(__float2bfloat16(p2));
            float h3 = __bfloat162float(__float2bfloat16(p3));
            const int kc = nt >> 1, hf = (nt & 1) * 2;
            aPh[kc][hf] = pack_bf2(p0, p1);
            aPh[kc][hf + 1] = pack_bf2(p2, p3);
            aPl[kc][hf] = pack_bf2(p0 - h0, p1 - h1);
            aPl[kc][hf + 1] = pack_bf2(p2 - h2, p3 - h3);
        }
        sum0 += __shfl_xor_sync(0xffffffffu, sum0, 1);
        sum0 += __shfl_xor_sync(0xffffffffu, sum0, 2);
        sum1 += __shfl_xor_sync(0xffffffffu, sum1, 1);
        sum1 += __shfl_xor_sync(0xffffffffu, sum1, 2);
        l_0 = l_0 * al0 + sum0;
        l_1 = l_1 * al1 + sum1;

#pragma unroll
        for (int i = 0; i < 16; i++) {
            o[i][0] *= al0; o[i][1] *= al0;
            o[i][2] *= al1; o[i][3] *= al1;
        }

        const int vrow0 = (lane & 7) + (((lane >> 3) & 1) << 3);
        const int vcbl = (lane >> 4) << 4;
#pragma unroll
        for (int kc = 0; kc < 4; kc++) {
            const int vr = kc * 16 + vrow0;
#pragma unroll
            for (int nb = 0; nb < 8; nb++) {
                unsigned vh_[4], vl_[4];
                const int vcb = nb * 32 + vcbl;
                LDSM_X4T(vh_, sV_h + sw256(vr, vcb));
                LDSM_X4T(vl_, sV_l + sw256(vr, vcb));
                mma16816(o[2 * nb], aPh[kc], vh_[0], vh_[1]);
                mma16816(o[2 * nb + 1], aPh[kc], vh_[2], vh_[3]);
                mma16816(o[2 * nb], aPh[kc], vl_[0], vl_[1]);
                mma16816(o[2 * nb + 1], aPh[kc], vl_[2], vl_[3]);
                mma16816(o[2 * nb], aPl[kc], vh_[0], vh_[1]);
                mma16816(o[2 * nb + 1], aPl[kc], vh_[2], vh_[3]);
            }
        }
        __syncthreads();
    }

    const float inv0 = 1.0f / l_0, inv1 = 1.0f / l_1;
    const int row0 = q0 + m0 + gp;
#pragma unroll
    for (int nt = 0; nt < 16; nt++) {
        const int col = h * 128 + nt * 8 + tig * 2;
        *(float2*)(O + (size_t)row0 * HIDW + col) =
            make_float2(o[nt][0] * inv0, o[nt][1] * inv0);
        *(float2*)(O + (size_t)(row0 + 8) * HIDW + col) =
            make_float2(o[nt][2] * inv1, o[nt][3] * inv1);
    }
}

// ---------------------------------------------------------------------------
// Fused rms + rope + bf16-split: warp-per-head, thread-owns-4-dims.
// grid 4224 blocks x 256 threads (8 warps = 8 heads/iter, 3 iters). No barriers.
// grid.x: [0,1536) Q | [1536,3072) K | [3072,4096) IPQ | [4096,4224) IPK
// ---------------------------------------------------------------------------
__global__ __launch_bounds__(256) void fuse_qk_kernel(
    const float* __restrict__ Qb, const float* __restrict__ Kb,
    const float* __restrict__ EQb, const float* __restrict__ EKb,
    const float* __restrict__ IPKb,
    const float* __restrict__ nqw, const float* __restrict__ nkw,
    const float* __restrict__ naqw, const float* __restrict__ nakw,
    const float* __restrict__ nipq, const float* __restrict__ nipk,
    const float* __restrict__ cosT, const float* __restrict__ sinT,
    __nv_bfloat16* __restrict__ bh, __nv_bfloat16* __restrict__ bl)
{
    const int r = blockIdx.x;
    const int w = threadIdx.x >> 5, lane = threadIdx.x & 31;

    const float* src;
    const float* wv;
    size_t obase;
    int row_out;
    bool do_rope;

    if (r < 1536) {
        row_out = r; do_rope = true; obase = OFF_QF;
        if (r < 512) { src = EQb + (size_t)r * HIDW; wv = naqw; }
        else         { src = Qb + (size_t)(r - 512) * HIDW; wv = nqw; }
    } else if (r < 3072) {
        row_out = r - 1536; do_rope = true; obase = OFF_KF;
        if (row_out < 512) { src = EKb + (size_t)row_out * HIDW; wv = nakw; }
        else               { src = Kb + (size_t)(row_out - 512) * HIDW; wv = nkw; }
    } else if (r < 4096) {
        row_out = r - 3072; do_rope = false; obase = OFF_IPQ;
        src = Qb + (size_t)row_out * HIDW; wv = nipq;
    } else {
        row_out = r - 4096; do_rope = false; obase = OFF_IPK;
        src = IPKb + (size_t)row_out * HIDW; wv = nipk;
    }

    const int d4 = lane * 4;
    const float4 wvv = *(const float4*)(wv + d4);
    float4 cs = make_float4(0, 0, 0, 0), sn = cs;
    if (do_rope) {
        cs = *(const float4*)(cosT + row_out * DHW + d4);
        sn = *(const float4*)(sinT + row_out * DHW + d4);
    }
    obase += (size_t)row_out * HIDW + d4;

#pragma unroll
    for (int hi = 0; hi < 3; hi++) {
        const int h = hi * 8 + w;
        float4 x = *(const float4*)(src + h * DHW + d4);
        float v = x.x * x.x + x.y * x.y + x.z * x.z + x.w * x.w;
#pragma unroll
        for (int off = 16; off > 0; off >>= 1)
            v += __shfl_xor_sync(0xffffffffu, v, off);
        const float rinv = rsqrtf(v * (1.0f / 128.0f) + 1e-6f);
        float y0 = x.x * rinv * wvv.x;
        float y1 = x.y * rinv * wvv.y;
        float y2 = x.z * rinv * wvv.z;
        float y3 = x.w * rinv * wvv.w;
        if (do_rope) {
            float r0 = y0 * cs.x - y1 * sn.x;
            float r1 = y1 * cs.y + y0 * sn.y;
            float r2 = y2 * cs.z - y3 * sn.z;
            float r3 = y3 * cs.w + y2 * sn.w;
            y0 = r0; y1 = r1; y2 = r2; y3 = r3;
        }
        unsigned h01 = pack_bf2(y0, y1);
        unsigned h23 = pack_bf2(y2, y3);
        float f0 = __bfloat162float(__float2bfloat16(y0));
        float f1 = __bfloat162float(__float2bfloat16(y1));
        float f2 = __bfloat162float(__float2bfloat16(y2));
        float f3 = __bfloat162float(__float2bfloat16(y3));
        unsigned l01 = pack_bf2(y0 - f0, y1 - f1);
        unsigned l23 = pack_bf2(y2 - f2, y3 - f3);
        *(uint2*)(bh + obase + h * DHW) = make_uint2(h01, h23);
        *(uint2*)(bl + obase + h * DHW) = make_uint2(l01, l23);
    }
}

// ---------------------------------------------------------------------------
// maskadd in place on fp32 attention output (bbox only). grid 256, block 256.
// ---------------------------------------------------------------------------
__global__ __launch_bounds__(256) void maskadd_kernel(
    float* __restrict__ Aimg, const float* __restrict__ IPO)
{
    const int bi = blockIdx.x;                 // 0..255 within bbox
    const int y = 8 + (bi >> 4), x = 8 + (bi & 15);
    const int i = y * 32 + x;
    float* a = Aimg + (size_t)i * HIDW;
    const float* p = IPO + (size_t)i * HIDW;
#pragma unroll
    for (int c = 0; c < HIDW / 256; c++)
        a[c * 256 + threadIdx.x] += p[c * 256 + threadIdx.x];
}

// ---------------------------------------------------------------------------
extern "C" void kernel_launch(void* const* d_in, const int* in_sizes, int n_in,
                              void* d_out, int out_size)
{
    const float* hs    = (const float*)d_in[0];
    const float* enc   = (const float*)d_in[1];
    const float* ip    = (const float*)d_in[2];
    const float* cosT  = (const float*)d_in[3];
    const float* sinT  = (const float*)d_in[4];
    const float* Wq    = (const float*)d_in[5];
    const float* bq    = (const float*)d_in[6];
    const float* Wk    = (const float*)d_in[7];
    const float* bk    = (const float*)d_in[8];
    const float* Wv    = (const float*)d_in[9];
    const float* bv    = (const float*)d_in[10];
    const float* nqw   = (const float*)d_in[11];
    const float* nkw   = (const float*)d_in[12];
    const float* Wqa   = (const float*)d_in[13];
    const float* bqa   = (const float*)d_in[14];
    const float* Wka   = (const float*)d_in[15];
    const float* bka   = (const float*)d_in[16];
    const float* Wva   = (const float*)d_in[17];
    const float* bva   = (const float*)d_in[18];
    const float* naqw  = (const float*)d_in[19];
    const float* nakw  = (const float*)d_in[20];
    const float* Wout  = (const float*)d_in[21];
    const float* bout  = (const float*)d_in[22];
    const float* Waout = (const float*)d_in[23];
    const float* baout = (const float*)d_in[24];
    const float* Wkip  = (const float*)d_in[25];
    const float* bkip  = (const float*)d_in[26];
    const float* Wvip  = (const float*)d_in[27];
    const float* bvip  = (const float*)d_in[28];
    const float* nipq  = (const float*)d_in[29];
    const float* nipk  = (const float*)d_in[30];

    float* buf = nullptr;
    cudaGetSymbolAddress((void**)&buf, g_buf);
    __nv_bfloat16* bh = nullptr;
    __nv_bfloat16* bl = nullptr;
    cudaGetSymbolAddress((void**)&bh, g_bh);
    cudaGetSymbolAddress((void**)&bl, g_bl);

    float* Qb   = buf + (size_t)O_Q * HIDW;
    float* Kb   = buf + (size_t)O_K * HIDW;
    float* EQb  = buf + (size_t)O_EQ * HIDW;
    float* EKb  = buf + (size_t)O_EK * HIDW;
    float* IPKb = buf + (size_t)O_IPK * HIDW;
    float* ATb  = buf + (size_t)O_ATTN * HIDW;
    float* IPOb = buf + (size_t)O_IPOUT * HIDW;

    float* out_img = (float*)d_out;
    float* out_enc = (float*)d_out + (size_t)IMGN * HIDW;

    const int smem_gemm = 98304;
    const int smem_fa   = 196608;
    cudaFuncSetAttribute(gemm_multi_kernel, cudaFuncAttributeMaxDynamicSharedMemorySize,
                         smem_gemm);
    cudaFuncSetAttribute(flash_kernel, cudaFuncAttributeMaxDynamicSharedMemorySize,
                         smem_fa);

    // ---- 1) all 8 projections in one GEMM launch (fp32 inputs directly) ----
    {
        GJobs gj;
        gj.njobs = 8;
        auto setj = [&](int i, const float* A, const float* B, const float* bias,
                        float* C, __nv_bfloat16* Oh, __nv_bfloat16* Ol,
                        int M, int K, int& blk) {
            gj.j[i].A = A; gj.j[i].B = B; gj.j[i].bias = bias;
            gj.j[i].C = C; gj.j[i].Oh = Oh; gj.j[i].Ol = Ol;
            gj.j[i].K = K; gj.j[i].blk0 = blk;
            gj.j[i].mode = (Oh != nullptr) ? 1 : 0;
            blk += (M / 128) * 24;
        };
        int blk = 0;
        setj(0, hs, Wq, bq, Qb, nullptr, nullptr, IMGN, HIDW, blk);
        setj(1, hs, Wk, bk, Kb, nullptr, nullptr, IMGN, HIDW, blk);
        setj(2, hs, Wv, bv, nullptr,
             bh + OFF_VF + (size_t)TXTN * HIDW, bl + OFF_VF + (size_t)TXTN * HIDW,
             IMGN, HIDW, blk);
        setj(3, enc, Wqa, bqa, EQb, nullptr, nullptr, TXTN, HIDW, blk);
        setj(4, enc, Wka, bka, EKb, nullptr, nullptr, TXTN, HIDW, blk);
        setj(5, enc, Wva, bva, nullptr,
             bh + OFF_VF, bl + OFF_VF, TXTN, HIDW, blk);
        setj(6, ip, Wkip, bkip, IPKb, nullptr, nullptr, 128, 1152, blk);
        setj(7, ip, Wvip, bvip, nullptr,
             bh + OFF_IPV, bl + OFF_IPV, 128, 1152, blk);
        gemm_multi_kernel<<<blk, 256, smem_gemm>>>(gj);
    }

    // ---- 2) fused rms + rope + split ----
    fuse_qk_kernel<<<4224, 256>>>(
        Qb, Kb, EQb, EKb, IPKb, nqw, nkw, naqw, nakw, nipq, nipk,
        cosT, sinT, bh, bl);

    // ---- 3) flash attention ----
    flash_kernel<<<dim3(S_ALL / 128, NHW), 256, smem_fa>>>(
        bh + OFF_QF, bl + OFF_QF, bh + OFF_KF, bl + OFF_KF,
        bh + OFF_VF, bl + OFF_VF, ATb, S_ALL);
    flash_kernel<<<dim3(IMGN / 128, NHW), 256, smem_fa>>>(
        bh + OFF_IPQ, bl + OFF_IPQ, bh + OFF_IPK, bl + OFF_IPK,
        bh + OFF_IPV, bl + OFF_IPV, IPOb, 128);

    // ---- 4) maskadd in place on img rows of ATb ----
    maskadd_kernel<<<256, 256>>>(ATb + (size_t)TXTN * HIDW, IPOb);

    // ---- 5) output projections in one GEMM launch (fp32 A from ATb) ----
    {
        GJobs gj;
        gj.njobs = 2;
        int blk = 0;
        gj.j[0].A = ATb + (size_t)TXTN * HIDW; gj.j[0].B = Wout;
        gj.j[0].bias = bout; gj.j[0].C = out_img;
        gj.j[0].Oh = nullptr; gj.j[0].Ol = nullptr;
        gj.j[0].K = HIDW; gj.j[0].blk0 = blk; gj.j[0].mode = 0;
        blk += (IMGN / 128) * 24;
        gj.j[1].A = ATb; gj.j[1].B = Waout;
        gj.j[1].bias = baout; gj.j[1].C = out_enc;
        gj.j[1].Oh = nullptr; gj.j[1].Ol = nullptr;
        gj.j[1].K = HIDW; gj.j[1].blk0 = blk; gj.j[1].mode = 0;
        blk += (TXTN / 128) * 24;
        gemm_multi_kernel<<<blk, 256, smem_gemm>>>(gj);
    }
}